// round 1
// baseline (speedup 1.0000x reference)
#include <cuda_runtime.h>
#include <math.h>

// Shapes (fixed by the problem)
#define CB 4
#define CT 2048
#define CC 1024
#define CH 16
#define CD 64
#define CM (CB*CT)     // 8192 rows
#define C3 (3*CC)      // 3072

// Scratch (device globals — no allocations allowed)
__device__ float g_q[(size_t)CB*CH*CT*CD];   // [B,H,T,D]
__device__ float g_k[(size_t)CB*CH*CT*CD];
__device__ float g_v[(size_t)CB*CH*CT*CD];
__device__ float g_y[(size_t)CM*CC];         // attention output, [B,T,C]
__device__ float g_cos[CT*32];
__device__ float g_sin[CT*32];

// ---------------------------------------------------------------------------
// RoPE tables: cos/sin(t * 10000^{-(2i)/64}) computed to match reference fp32
// ---------------------------------------------------------------------------
__global__ void rope_table_kernel() {
    int idx = blockIdx.x * blockDim.x + threadIdx.x;
    if (idx >= CT * 32) return;
    int t = idx >> 5;
    int i = idx & 31;
    double dinv = pow(10000.0, -(double)(2 * i) / 64.0);
    float invf = (float)dinv;          // reference rounds inv_freq to f32
    float ang = (float)t * invf;       // then multiplies in f32
    g_cos[idx] = cosf(ang);
    g_sin[idx] = sinf(ang);
}

// ---------------------------------------------------------------------------
// QKV GEMM (8192x1024 @ 1024x3072) + RoPE epilogue + scatter to [B,H,T,D]
// 128x128 tile, BK=16, 256 threads, 8x8 per thread
// ---------------------------------------------------------------------------
__global__ __launch_bounds__(256)
void qkv_rope_kernel(const float* __restrict__ X, const float* __restrict__ W) {
    __shared__ float As[16][128];
    __shared__ float Bs[16][128];
    const int tid = threadIdx.x;
    const int ty = tid >> 4, tx = tid & 15;
    const int bm = blockIdx.y, bn = blockIdx.x;
    const int arow = tid >> 2, acol4 = tid & 3;
    const int brow = tid >> 5, bcol4 = tid & 31;
    const float* Ag = X + (size_t)(bm * 128) * CC;
    const float* Bg = W + bn * 128;

    float acc[8][8];
#pragma unroll
    for (int i = 0; i < 8; i++)
#pragma unroll
        for (int j = 0; j < 8; j++) acc[i][j] = 0.f;

    for (int k0 = 0; k0 < CC; k0 += 16) {
#pragma unroll
        for (int r = 0; r < 2; r++) {
            int row = arow + r * 64;
            float4 v = *(const float4*)(Ag + (size_t)row * CC + k0 + acol4 * 4);
            As[acol4 * 4 + 0][row] = v.x;
            As[acol4 * 4 + 1][row] = v.y;
            As[acol4 * 4 + 2][row] = v.z;
            As[acol4 * 4 + 3][row] = v.w;
        }
#pragma unroll
        for (int r = 0; r < 2; r++) {
            int row = brow + r * 8;
            *(float4*)&Bs[row][bcol4 * 4] =
                *(const float4*)(Bg + (size_t)(k0 + row) * C3 + bcol4 * 4);
        }
        __syncthreads();
#pragma unroll
        for (int k = 0; k < 16; k++) {
            float a[8], b[8];
            *(float4*)(a)     = *(float4*)&As[k][ty * 8];
            *(float4*)(a + 4) = *(float4*)&As[k][ty * 8 + 4];
            *(float4*)(b)     = *(float4*)&Bs[k][tx * 8];
            *(float4*)(b + 4) = *(float4*)&Bs[k][tx * 8 + 4];
#pragma unroll
            for (int i = 0; i < 8; i++)
#pragma unroll
                for (int j = 0; j < 8; j++)
                    acc[i][j] = fmaf(a[i], b[j], acc[i][j]);
        }
        __syncthreads();
    }

    // Epilogue: all 8 cols of a thread live in one segment (q/k/v) & one head
    const int col0 = bn * 128 + tx * 8;
    const int seg = col0 >> 10;        // 0=q 1=k 2=v
    const int cs = col0 & 1023;
    const int h = cs >> 6, dbase = cs & 63;
    float* base = (seg == 0) ? g_q : ((seg == 1) ? g_k : g_v);

#pragma unroll
    for (int i = 0; i < 8; i++) {
        int r = bm * 128 + ty * 8 + i;
        int b = r >> 11, t = r & 2047;
        float* dst = base + (((size_t)(b * CH + h) * CT + t) * CD + dbase);
        if (seg == 2) {
#pragma unroll
            for (int j = 0; j < 8; j++) dst[j] = acc[i][j];
        } else {
#pragma unroll
            for (int p = 0; p < 4; p++) {
                int fi = (dbase >> 1) + p;
                float c = g_cos[t * 32 + fi];
                float s = g_sin[t * 32 + fi];
                float x1 = acc[i][2 * p], x2 = acc[i][2 * p + 1];
                dst[2 * p]     = x1 * c - x2 * s;
                dst[2 * p + 1] = x1 * s + x2 * c;
            }
        }
    }
}

// ---------------------------------------------------------------------------
// Causal flash attention, fp32. BM=128 q-rows, BN=64 kv-rows, 256 threads.
// Thread (ty,tx): rows ty+16i (i<8), cols tx+16j (j<4).
// Smem (dynamic 80KB): Qs (swizzled, 32KB) | U = K(swz,16KB)/P(plain,32KB) | Vt(swz,16KB)
// All inner-loop LDS.128 are XOR-swizzled conflict-free.
// ---------------------------------------------------------------------------
__global__ __launch_bounds__(256)
void attn_kernel() {
    extern __shared__ float sm[];
    float4* Qs4 = (float4*)sm;                 // 128*16 float4
    float4* U4  = (float4*)(sm + 8192);        // K swz (64*16) / P plain (128*16)
    float4* Vs4 = (float4*)(sm + 16384);       // V^T swz (64*16)
    float*  Uf  = sm + 8192;
    float*  Vf  = sm + 16384;

    const int tid = threadIdx.x;
    const int ty = tid >> 4, tx = tid & 15;
    const int bh = blockIdx.y;
    const int qb = gridDim.x - 1 - blockIdx.x;     // heavy tiles first
    const int q0 = qb * 128;
    const float* Qg = g_q + (size_t)bh * CT * CD;
    const float* Kg = g_k + (size_t)bh * CT * CD;
    const float* Vg = g_v + (size_t)bh * CT * CD;

    // Q tile (swizzled by row&15)
#pragma unroll
    for (int r = 0; r < 8; r++) {
        int vecid = tid + 256 * r;
        int row = vecid >> 4, d4 = vecid & 15;
        Qs4[row * 16 + (d4 ^ (row & 15))] =
            *(const float4*)(Qg + (size_t)(q0 + row) * CD + d4 * 4);
    }

    float o[8][4], m[8], l[8];
#pragma unroll
    for (int i = 0; i < 8; i++) {
        m[i] = -3.0e38f; l[i] = 0.f;
#pragma unroll
        for (int j = 0; j < 4; j++) o[i][j] = 0.f;
    }

    const int ntiles = 2 * qb + 2;
    for (int n = 0; n < ntiles; n++) {
        const int k0 = n * 64;
        __syncthreads();   // prev O-update reads of U/Vt done; also covers Q load (n=0)

        // K tile, swizzled
#pragma unroll
        for (int r = 0; r < 4; r++) {
            int vecid = tid + 256 * r;
            int c = vecid >> 4, d4 = vecid & 15;
            U4[c * 16 + (d4 ^ (c & 15))] =
                *(const float4*)(Kg + (size_t)(k0 + c) * CD + d4 * 4);
        }
        // V tile, transposed + swizzled: Vt[d][k]
#pragma unroll
        for (int r = 0; r < 4; r++) {
            int vecid = tid + 256 * r;
            int row = vecid >> 4, d4 = vecid & 15;
            float4 v = *(const float4*)(Vg + (size_t)(k0 + row) * CD + d4 * 4);
            float vv[4] = {v.x, v.y, v.z, v.w};
#pragma unroll
            for (int lq = 0; lq < 4; lq++) {
                int cc = d4 * 4 + lq;
                Vf[cc * 64 + ((((row >> 2) ^ (cc & 15)) << 2) | (row & 3))] = vv[lq];
            }
        }
        __syncthreads();

        // S = Q K^T
        float sacc[8][4];
#pragma unroll
        for (int i = 0; i < 8; i++)
#pragma unroll
            for (int j = 0; j < 4; j++) sacc[i][j] = 0.f;
#pragma unroll
        for (int d4 = 0; d4 < 16; d4++) {
            float4 bq[4];
#pragma unroll
            for (int j = 0; j < 4; j++)
                bq[j] = U4[(tx + 16 * j) * 16 + (d4 ^ tx)];
#pragma unroll
            for (int i = 0; i < 8; i++) {
                float4 aq = Qs4[(ty + 16 * i) * 16 + (d4 ^ ty)];
#pragma unroll
                for (int j = 0; j < 4; j++) {
                    sacc[i][j] = fmaf(aq.x, bq[j].x, sacc[i][j]);
                    sacc[i][j] = fmaf(aq.y, bq[j].y, sacc[i][j]);
                    sacc[i][j] = fmaf(aq.z, bq[j].z, sacc[i][j]);
                    sacc[i][j] = fmaf(aq.w, bq[j].w, sacc[i][j]);
                }
            }
        }

        // scale + causal mask + online softmax
        const float scale = 0.125f;   // 1/sqrt(64)
        const bool diag = (n >= 2 * qb);
#pragma unroll
        for (int i = 0; i < 8; i++) {
            int qi = q0 + ty + 16 * i;
#pragma unroll
            for (int j = 0; j < 4; j++) {
                float s = sacc[i][j] * scale;
                if (diag && (k0 + tx + 16 * j > qi)) s = -3.0e38f;
                sacc[i][j] = s;
            }
            float rmax = fmaxf(fmaxf(sacc[i][0], sacc[i][1]),
                               fmaxf(sacc[i][2], sacc[i][3]));
            rmax = fmaxf(rmax, __shfl_xor_sync(0xffffffffu, rmax, 8, 16));
            rmax = fmaxf(rmax, __shfl_xor_sync(0xffffffffu, rmax, 4, 16));
            rmax = fmaxf(rmax, __shfl_xor_sync(0xffffffffu, rmax, 2, 16));
            rmax = fmaxf(rmax, __shfl_xor_sync(0xffffffffu, rmax, 1, 16));
            float mnew = fmaxf(m[i], rmax);
            float sf = __expf(m[i] - mnew);
            float rsum = 0.f;
#pragma unroll
            for (int j = 0; j < 4; j++) {
                float p = __expf(sacc[i][j] - mnew);
                sacc[i][j] = p;
                rsum += p;
            }
            rsum += __shfl_xor_sync(0xffffffffu, rsum, 8, 16);
            rsum += __shfl_xor_sync(0xffffffffu, rsum, 4, 16);
            rsum += __shfl_xor_sync(0xffffffffu, rsum, 2, 16);
            rsum += __shfl_xor_sync(0xffffffffu, rsum, 1, 16);
            l[i] = l[i] * sf + rsum;
            m[i] = mnew;
#pragma unroll
            for (int j = 0; j < 4; j++) o[i][j] *= sf;
        }

        __syncthreads();   // S-phase reads of K (in U) done; overwrite U with P
#pragma unroll
        for (int i = 0; i < 8; i++)
#pragma unroll
            for (int j = 0; j < 4; j++)
                Uf[(ty + 16 * i) * 64 + (tx + 16 * j)] = sacc[i][j];
        __syncthreads();

        // O += P V
#pragma unroll
        for (int k4 = 0; k4 < 16; k4++) {
            float4 vv[4];
#pragma unroll
            for (int j = 0; j < 4; j++)
                vv[j] = Vs4[(tx + 16 * j) * 16 + (k4 ^ tx)];
#pragma unroll
            for (int i = 0; i < 8; i++) {
                float4 pp = U4[(ty + 16 * i) * 16 + k4];
#pragma unroll
                for (int j = 0; j < 4; j++) {
                    o[i][j] = fmaf(pp.x, vv[j].x, o[i][j]);
                    o[i][j] = fmaf(pp.y, vv[j].y, o[i][j]);
                    o[i][j] = fmaf(pp.z, vv[j].z, o[i][j]);
                    o[i][j] = fmaf(pp.w, vv[j].w, o[i][j]);
                }
            }
        }
    }

    // write y in [B,T,C] layout (c = h*64 + d)
    const int b = bh >> 4, h = bh & 15;
#pragma unroll
    for (int i = 0; i < 8; i++) {
        float invl = 1.f / l[i];
        int qi = q0 + ty + 16 * i;
        float* dst = g_y + ((size_t)(b * CT + qi)) * CC + h * CD;
#pragma unroll
        for (int j = 0; j < 4; j++)
            dst[tx + 16 * j] = o[i][j] * invl;
    }
}

// ---------------------------------------------------------------------------
// Output projection: (8192x1024) @ (1024x1024) -> d_out
// ---------------------------------------------------------------------------
__global__ __launch_bounds__(256)
void proj_kernel(const float* __restrict__ W, float* __restrict__ out) {
    __shared__ float As[16][128];
    __shared__ float Bs[16][128];
    const int tid = threadIdx.x;
    const int ty = tid >> 4, tx = tid & 15;
    const int bm = blockIdx.y, bn = blockIdx.x;
    const int arow = tid >> 2, acol4 = tid & 3;
    const int brow = tid >> 5, bcol4 = tid & 31;
    const float* Ag = g_y + (size_t)(bm * 128) * CC;
    const float* Bg = W + bn * 128;

    float acc[8][8];
#pragma unroll
    for (int i = 0; i < 8; i++)
#pragma unroll
        for (int j = 0; j < 8; j++) acc[i][j] = 0.f;

    for (int k0 = 0; k0 < CC; k0 += 16) {
#pragma unroll
        for (int r = 0; r < 2; r++) {
            int row = arow + r * 64;
            float4 v = *(const float4*)(Ag + (size_t)row * CC + k0 + acol4 * 4);
            As[acol4 * 4 + 0][row] = v.x;
            As[acol4 * 4 + 1][row] = v.y;
            As[acol4 * 4 + 2][row] = v.z;
            As[acol4 * 4 + 3][row] = v.w;
        }
#pragma unroll
        for (int r = 0; r < 2; r++) {
            int row = brow + r * 8;
            *(float4*)&Bs[row][bcol4 * 4] =
                *(const float4*)(Bg + (size_t)(k0 + row) * CC + bcol4 * 4);
        }
        __syncthreads();
#pragma unroll
        for (int k = 0; k < 16; k++) {
            float a[8], b[8];
            *(float4*)(a)     = *(float4*)&As[k][ty * 8];
            *(float4*)(a + 4) = *(float4*)&As[k][ty * 8 + 4];
            *(float4*)(b)     = *(float4*)&Bs[k][tx * 8];
            *(float4*)(b + 4) = *(float4*)&Bs[k][tx * 8 + 4];
#pragma unroll
            for (int i = 0; i < 8; i++)
#pragma unroll
                for (int j = 0; j < 8; j++)
                    acc[i][j] = fmaf(a[i], b[j], acc[i][j]);
        }
        __syncthreads();
    }

#pragma unroll
    for (int i = 0; i < 8; i++) {
        int r = bm * 128 + ty * 8 + i;
        float* dst = out + (size_t)r * CC + bn * 128 + tx * 8;
        *(float4*)(dst)     = *(float4*)&acc[i][0];
        *(float4*)(dst + 4) = *(float4*)&acc[i][4];
    }
}

// ---------------------------------------------------------------------------
extern "C" void kernel_launch(void* const* d_in, const int* in_sizes, int n_in,
                              void* d_out, int out_size) {
    const float* x      = (const float*)d_in[0];
    const float* W_attn = (const float*)d_in[1];
    const float* W_proj = (const float*)d_in[2];
    float* out = (float*)d_out;
    (void)in_sizes; (void)n_in; (void)out_size;

    rope_table_kernel<<<(CT * 32 + 255) / 256, 256>>>();

    dim3 g1(C3 / 128, CM / 128);
    qkv_rope_kernel<<<g1, 256>>>(x, W_attn);

    cudaFuncSetAttribute(attn_kernel,
                         cudaFuncAttributeMaxDynamicSharedMemorySize, 81920);
    dim3 g2(CT / 128, CB * CH);
    attn_kernel<<<g2, 256, 81920>>>();

    dim3 g3(CC / 128, CM / 128);
    proj_kernel<<<g3, 256>>>(W_proj, out);
}

// round 12
// speedup vs baseline: 1.2695x; 1.2695x over previous
#include <cuda_runtime.h>
#include <cuda_bf16.h>
#include <math.h>
#include <stdint.h>

// Shapes (fixed)
#define CB 4
#define CT 2048
#define CC 1024
#define CH 16
#define CD 64
#define CM (CB*CT)     // 8192
#define C3 (3*CC)      // 3072

// ---------------- device scratch: EXACT R1 set (proven to pass) ------------
__device__ float g_q[(size_t)CB*CH*CT*CD];
__device__ float g_k[(size_t)CB*CH*CT*CD];
__device__ float g_v[(size_t)CB*CH*CT*CD];
__device__ float g_y[(size_t)CM*CC];
__device__ float g_cos[CT*32];
__device__ float g_sin[CT*32];

// ---------------- PTX helpers (compute_100-safe only) -----------------------
__device__ __forceinline__ uint32_t smem_u32(const void* p) {
    uint32_t a;
    asm("{ .reg .u64 t; cvta.to.shared.u64 t, %1; cvt.u32.u64 %0, t; }" : "=r"(a) : "l"(p));
    return a;
}
#define LDSM4(r0,r1,r2,r3,addr) \
    asm volatile("ldmatrix.sync.aligned.m8n8.x4.shared.b16 {%0,%1,%2,%3}, [%4];" \
                 : "=r"(r0), "=r"(r1), "=r"(r2), "=r"(r3) : "r"(addr))
#define MMA16816(d, a0, a1, a2, a3, b0, b1) \
    asm volatile("mma.sync.aligned.m16n8k16.row.col.f32.bf16.bf16.f32 " \
                 "{%0,%1,%2,%3}, {%4,%5,%6,%7}, {%8,%9}, {%0,%1,%2,%3};" \
                 : "+f"((d)[0]), "+f"((d)[1]), "+f"((d)[2]), "+f"((d)[3]) \
                 : "r"(a0), "r"(a1), "r"(a2), "r"(a3), "r"(b0), "r"(b1))

__device__ __forceinline__ uint32_t pack2(float a, float b) {
    __nv_bfloat16 ha = __float2bfloat16_rn(a);
    __nv_bfloat16 hb = __float2bfloat16_rn(b);
    uint16_t ua = *(uint16_t*)&ha, ub = *(uint16_t*)&hb;
    return (uint32_t)ua | ((uint32_t)ub << 16);
}
__device__ __forceinline__ float bf16_val(float v) {
    __nv_bfloat16 h = __float2bfloat16_rn(v);
    return __bfloat162float(h);
}

// ---------------------------------------------------------------------------
// RoPE tables (R1 verbatim)
// ---------------------------------------------------------------------------
__global__ void rope_table_kernel() {
    int idx = blockIdx.x * blockDim.x + threadIdx.x;
    if (idx >= CT * 32) return;
    int t = idx >> 5;
    int i = idx & 31;
    double dinv = pow(10000.0, -(double)(2 * i) / 64.0);
    float invf = (float)dinv;
    float ang = (float)t * invf;
    g_cos[idx] = cosf(ang);
    g_sin[idx] = sinf(ang);
}

// ---------------------------------------------------------------------------
// Split-bf16 HMMA GEMM with fully in-kernel conversion (NO bf16 globals,
// NO cp.async, NO dynamic smem). C = Ah.Wh^T + Ah.Wl^T + Al.Wh^T.
// K=1024, BK=16 (64 chunks), 128x128 block, 512 threads = 16 warps (4x4),
// warp tile 32x32 (acc = 32 regs). Static smem: 8 tiles x 128x24 bf16 = 48KB.
// W is fp32 [K, N] k-major; split + transposed into smem per chunk.
// MODE 0: qkv (A=x, W=W_attn, N=3072) -> RoPE + scatter to g_q/g_k/g_v.
// MODE 1: proj (A=g_y, W=W_proj, N=1024) -> Out (d_out).
// ---------------------------------------------------------------------------
#define LDA 24
#define TILE 3072   // 128*24 elems

template<int MODE>
__global__ __launch_bounds__(512)
void hmma_gemm_kernel(const float* __restrict__ Asrc,
                      const float* __restrict__ Wsrc,
                      float* __restrict__ Out) {
    __shared__ __nv_bfloat16 sm_[8 * TILE];   // 49152 B (static limit)
    const uint32_t uS = smem_u32(sm_);
    const int N = (MODE == 0) ? C3 : CC;
    const int tid = threadIdx.x;
    const int wid = tid >> 5, lane = tid & 31;
    const int wm = wid >> 2, wn = wid & 3;          // 4x4 warp grid
    const int m0 = blockIdx.y * 128, n0 = blockIdx.x * 128;
    const float* __restrict__ Ap = (MODE == 0) ? (Asrc + (size_t)m0 * CC)
                                               : (g_y + (size_t)m0 * CC);

    // A staging: thread -> row arow (0..127), quarter aq (4 floats)
    const int arow = tid >> 2;
    const int aq = tid & 3;
    // W staging: thread -> n_local wn_ (0..127), k-quarter wk (4 k values)
    const int wn_ = tid & 127;
    const int wk = tid >> 7;

    float acc[2][4][4];
#pragma unroll
    for (int mi = 0; mi < 2; mi++)
#pragma unroll
        for (int ni = 0; ni < 4; ni++)
#pragma unroll
            for (int r = 0; r < 4; r++) acc[mi][ni][r] = 0.f;

    // ldmatrix lane addressing (elem offsets within a tile)
    const int aOff = (wm * 32 + (lane & 15)) * LDA + (lane >> 4) * 8;
    const int bOff = (wn * 32 + ((lane >> 4) & 1) * 8 + (lane & 7)) * LDA
                     + ((lane >> 3) & 1) * 8;

    // ---- stage chunk 0 into buffer 0 ----
    {
        float4 av = *(const float4*)(Ap + (size_t)arow * CC + aq * 4);
        const float* wp = Wsrc + (size_t)(wk * 4) * N + n0 + wn_;
        float w0 = wp[0], w1 = wp[N], w2 = wp[2 * (size_t)N], w3 = wp[3 * (size_t)N];
        __nv_bfloat16* Ah_ = sm_;
        __nv_bfloat16* Al_ = sm_ + 2 * TILE;
        __nv_bfloat16* Wh_ = sm_ + 4 * TILE;
        __nv_bfloat16* Wl_ = sm_ + 6 * TILE;
        int aoff = arow * LDA + aq * 4;
        *(uint2*)(Ah_ + aoff) = make_uint2(pack2(av.x, av.y), pack2(av.z, av.w));
        *(uint2*)(Al_ + aoff) = make_uint2(
            pack2(av.x - bf16_val(av.x), av.y - bf16_val(av.y)),
            pack2(av.z - bf16_val(av.z), av.w - bf16_val(av.w)));
        int woff = wn_ * LDA + wk * 4;
        *(uint32_t*)(Wh_ + woff)     = pack2(w0, w1);
        *(uint32_t*)(Wh_ + woff + 2) = pack2(w2, w3);
        *(uint32_t*)(Wl_ + woff)     = pack2(w0 - bf16_val(w0), w1 - bf16_val(w1));
        *(uint32_t*)(Wl_ + woff + 2) = pack2(w2 - bf16_val(w2), w3 - bf16_val(w3));
    }
    __syncthreads();

    for (int kc = 0; kc < 64; kc++) {
        const int buf = kc & 1;

        // issue next chunk's global loads early (results held in scalars)
        float4 av; float w0, w1, w2, w3;
        if (kc + 1 < 64) {
            av = *(const float4*)(Ap + (size_t)arow * CC + (kc + 1) * 16 + aq * 4);
            const float* wp = Wsrc + (size_t)((kc + 1) * 16 + wk * 4) * N + n0 + wn_;
            w0 = wp[0]; w1 = wp[N]; w2 = wp[2 * (size_t)N]; w3 = wp[3 * (size_t)N];
        }

        // ---- compute on buf ----
        const uint32_t bAh = uS + (uint32_t)(buf * TILE) * 2;
        const uint32_t bAl = uS + (uint32_t)(2 * TILE + buf * TILE) * 2;
        const uint32_t bWh = uS + (uint32_t)(4 * TILE + buf * TILE) * 2;
        const uint32_t bWl = uS + (uint32_t)(6 * TILE + buf * TILE) * 2;
        const uint32_t offB0 = (uint32_t)(bOff) * 2;
        const uint32_t offB1 = (uint32_t)(bOff + 16 * LDA) * 2;

        uint32_t wh0, wh1, wh2, wh3, wh4, wh5, wh6, wh7;
        uint32_t wl0, wl1, wl2, wl3, wl4, wl5, wl6, wl7;
        LDSM4(wh0, wh1, wh2, wh3, bWh + offB0);
        LDSM4(wh4, wh5, wh6, wh7, bWh + offB1);
        LDSM4(wl0, wl1, wl2, wl3, bWl + offB0);
        LDSM4(wl4, wl5, wl6, wl7, bWl + offB1);
#pragma unroll
        for (int mi = 0; mi < 2; mi++) {
            uint32_t offA = (uint32_t)(aOff + mi * 16 * LDA) * 2;
            uint32_t a0, a1, a2, a3;
            LDSM4(a0, a1, a2, a3, bAh + offA);
            MMA16816(acc[mi][0], a0, a1, a2, a3, wh0, wh1);
            MMA16816(acc[mi][1], a0, a1, a2, a3, wh2, wh3);
            MMA16816(acc[mi][2], a0, a1, a2, a3, wh4, wh5);
            MMA16816(acc[mi][3], a0, a1, a2, a3, wh6, wh7);
            MMA16816(acc[mi][0], a0, a1, a2, a3, wl0, wl1);
            MMA16816(acc[mi][1], a0, a1, a2, a3, wl2, wl3);
            MMA16816(acc[mi][2], a0, a1, a2, a3, wl4, wl5);
            MMA16816(acc[mi][3], a0, a1, a2, a3, wl6, wl7);
            LDSM4(a0, a1, a2, a3, bAl + offA);
            MMA16816(acc[mi][0], a0, a1, a2, a3, wh0, wh1);
            MMA16816(acc[mi][1], a0, a1, a2, a3, wh2, wh3);
            MMA16816(acc[mi][2], a0, a1, a2, a3, wh4, wh5);
            MMA16816(acc[mi][3], a0, a1, a2, a3, wh6, wh7);
        }

        __syncthreads();   // all reads of both buffers for this iter done

        if (kc + 1 < 64) {
            const int b2 = buf ^ 1;
            __nv_bfloat16* Ah_ = sm_ + b2 * TILE;
            __nv_bfloat16* Al_ = sm_ + 2 * TILE + b2 * TILE;
            __nv_bfloat16* Wh_ = sm_ + 4 * TILE + b2 * TILE;
            __nv_bfloat16* Wl_ = sm_ + 6 * TILE + b2 * TILE;
            int aoff = arow * LDA + aq * 4;
            *(uint2*)(Ah_ + aoff) = make_uint2(pack2(av.x, av.y), pack2(av.z, av.w));
            *(uint2*)(Al_ + aoff) = make_uint2(
                pack2(av.x - bf16_val(av.x), av.y - bf16_val(av.y)),
                pack2(av.z - bf16_val(av.z), av.w - bf16_val(av.w)));
            int woff = wn_ * LDA + wk * 4;
            *(uint32_t*)(Wh_ + woff)     = pack2(w0, w1);
            *(uint32_t*)(Wh_ + woff + 2) = pack2(w2, w3);
            *(uint32_t*)(Wl_ + woff)     = pack2(w0 - bf16_val(w0), w1 - bf16_val(w1));
            *(uint32_t*)(Wl_ + woff + 2) = pack2(w2 - bf16_val(w2), w3 - bf16_val(w3));
            __syncthreads();   // next buffer ready
        }
    }

    // ------------- epilogue --------------------------------------------------
    const int lrow = lane >> 2;
    const int lcol = (lane & 3) * 2;

#pragma unroll
    for (int mi = 0; mi < 2; mi++) {
#pragma unroll
        for (int rh = 0; rh < 2; rh++) {
            const int r = m0 + wm * 32 + mi * 16 + lrow + rh * 8;
            if (MODE == 1) {
                float* dst = Out + (size_t)r * CC + n0 + wn * 32 + lcol;
#pragma unroll
                for (int ni = 0; ni < 4; ni++)
                    *(float2*)(dst + ni * 8) =
                        make_float2(acc[mi][ni][2 * rh], acc[mi][ni][2 * rh + 1]);
            } else {
                const int bI = r >> 11, t = r & 2047;
                const float* ct = g_cos + t * 32;
                const float* st = g_sin + t * 32;
#pragma unroll
                for (int ni = 0; ni < 4; ni++) {
                    const int cg = n0 + wn * 32 + ni * 8 + lcol;
                    const int seg = cg >> 10;
                    const int cs = cg & 1023;
                    const int h = cs >> 6, d = cs & 63;
                    float* base = (seg == 0) ? g_q : ((seg == 1) ? g_k : g_v);
                    float* dst = base + (((size_t)(bI * CH + h) * CT + t) * CD + d);
                    float x1 = acc[mi][ni][2 * rh], x2 = acc[mi][ni][2 * rh + 1];
                    if (seg == 2) {
                        *(float2*)dst = make_float2(x1, x2);
                    } else {
                        float c = ct[d >> 1], s = st[d >> 1];
                        *(float2*)dst = make_float2(x1 * c - x2 * s, x1 * s + x2 * c);
                    }
                }
            }
        }
    }
}

// ---------------------------------------------------------------------------
// Causal flash attention, fp32 SIMT — R1 VERBATIM (writes g_y)
// ---------------------------------------------------------------------------
__global__ __launch_bounds__(256)
void attn_kernel() {
    extern __shared__ float sm[];
    float4* Qs4 = (float4*)sm;
    float4* U4  = (float4*)(sm + 8192);
    float4* Vs4 = (float4*)(sm + 16384);
    float*  Uf  = sm + 8192;
    float*  Vf  = sm + 16384;

    const int tid = threadIdx.x;
    const int ty = tid >> 4, tx = tid & 15;
    const int bh = blockIdx.y;
    const int qb = gridDim.x - 1 - blockIdx.x;
    const int q0 = qb * 128;
    const float* Qg = g_q + (size_t)bh * CT * CD;
    const float* Kg = g_k + (size_t)bh * CT * CD;
    const float* Vg = g_v + (size_t)bh * CT * CD;

#pragma unroll
    for (int r = 0; r < 8; r++) {
        int vecid = tid + 256 * r;
        int row = vecid >> 4, d4 = vecid & 15;
        Qs4[row * 16 + (d4 ^ (row & 15))] =
            *(const float4*)(Qg + (size_t)(q0 + row) * CD + d4 * 4);
    }

    float o[8][4], m[8], l[8];
#pragma unroll
    for (int i = 0; i < 8; i++) {
        m[i] = -3.0e38f; l[i] = 0.f;
#pragma unroll
        for (int j = 0; j < 4; j++) o[i][j] = 0.f;
    }

    const int ntiles = 2 * qb + 2;
    for (int n = 0; n < ntiles; n++) {
        const int k0 = n * 64;
        __syncthreads();

#pragma unroll
        for (int r = 0; r < 4; r++) {
            int vecid = tid + 256 * r;
            int c = vecid >> 4, d4 = vecid & 15;
            U4[c * 16 + (d4 ^ (c & 15))] =
                *(const float4*)(Kg + (size_t)(k0 + c) * CD + d4 * 4);
        }
#pragma unroll
        for (int r = 0; r < 4; r++) {
            int vecid = tid + 256 * r;
            int row = vecid >> 4, d4 = vecid & 15;
            float4 v = *(const float4*)(Vg + (size_t)(k0 + row) * CD + d4 * 4);
            float vv[4] = {v.x, v.y, v.z, v.w};
#pragma unroll
            for (int lq = 0; lq < 4; lq++) {
                int cc = d4 * 4 + lq;
                Vf[cc * 64 + ((((row >> 2) ^ (cc & 15)) << 2) | (row & 3))] = vv[lq];
            }
        }
        __syncthreads();

        float sacc[8][4];
#pragma unroll
        for (int i = 0; i < 8; i++)
#pragma unroll
            for (int j = 0; j < 4; j++) sacc[i][j] = 0.f;
#pragma unroll
        for (int d4 = 0; d4 < 16; d4++) {
            float4 bq[4];
#pragma unroll
            for (int j = 0; j < 4; j++)
                bq[j] = U4[(tx + 16 * j) * 16 + (d4 ^ tx)];
#pragma unroll
            for (int i = 0; i < 8; i++) {
                float4 aq = Qs4[(ty + 16 * i) * 16 + (d4 ^ ty)];
#pragma unroll
                for (int j = 0; j < 4; j++) {
                    sacc[i][j] = fmaf(aq.x, bq[j].x, sacc[i][j]);
                    sacc[i][j] = fmaf(aq.y, bq[j].y, sacc[i][j]);
                    sacc[i][j] = fmaf(aq.z, bq[j].z, sacc[i][j]);
                    sacc[i][j] = fmaf(aq.w, bq[j].w, sacc[i][j]);
                }
            }
        }

        const float scale = 0.125f;
        const bool diag = (n >= 2 * qb);
#pragma unroll
        for (int i = 0; i < 8; i++) {
            int qi = q0 + ty + 16 * i;
#pragma unroll
            for (int j = 0; j < 4; j++) {
                float s = sacc[i][j] * scale;
                if (diag && (k0 + tx + 16 * j > qi)) s = -3.0e38f;
                sacc[i][j] = s;
            }
            float rmax = fmaxf(fmaxf(sacc[i][0], sacc[i][1]),
                               fmaxf(sacc[i][2], sacc[i][3]));
            rmax = fmaxf(rmax, __shfl_xor_sync(0xffffffffu, rmax, 8, 16));
            rmax = fmaxf(rmax, __shfl_xor_sync(0xffffffffu, rmax, 4, 16));
            rmax = fmaxf(rmax, __shfl_xor_sync(0xffffffffu, rmax, 2, 16));
            rmax = fmaxf(rmax, __shfl_xor_sync(0xffffffffu, rmax, 1, 16));
            float mnew = fmaxf(m[i], rmax);
            float sf = __expf(m[i] - mnew);
            float rsum = 0.f;
#pragma unroll
            for (int j = 0; j < 4; j++) {
                float p = __expf(sacc[i][j] - mnew);
                sacc[i][j] = p;
                rsum += p;
            }
            rsum += __shfl_xor_sync(0xffffffffu, rsum, 8, 16);
            rsum += __shfl_xor_sync(0xffffffffu, rsum, 4, 16);
            rsum += __shfl_xor_sync(0xffffffffu, rsum, 2, 16);
            rsum += __shfl_xor_sync(0xffffffffu, rsum, 1, 16);
            l[i] = l[i] * sf + rsum;
            m[i] = mnew;
#pragma unroll
            for (int j = 0; j < 4; j++) o[i][j] *= sf;
        }

        __syncthreads();
#pragma unroll
        for (int i = 0; i < 8; i++)
#pragma unroll
            for (int j = 0; j < 4; j++)
                Uf[(ty + 16 * i) * 64 + (tx + 16 * j)] = sacc[i][j];
        __syncthreads();

#pragma unroll
        for (int k4 = 0; k4 < 16; k4++) {
            float4 vv[4];
#pragma unroll
            for (int j = 0; j < 4; j++)
                vv[j] = Vs4[(tx + 16 * j) * 16 + (k4 ^ tx)];
#pragma unroll
            for (int i = 0; i < 8; i++) {
                float4 pp = U4[(ty + 16 * i) * 16 + k4];
#pragma unroll
                for (int j = 0; j < 4; j++) {
                    o[i][j] = fmaf(pp.x, vv[j].x, o[i][j]);
                    o[i][j] = fmaf(pp.y, vv[j].y, o[i][j]);
                    o[i][j] = fmaf(pp.z, vv[j].z, o[i][j]);
                    o[i][j] = fmaf(pp.w, vv[j].w, o[i][j]);
                }
            }
        }
    }

    const int b = bh >> 4, h = bh & 15;
#pragma unroll
    for (int i = 0; i < 8; i++) {
        float invl = 1.f / l[i];
        int qi = q0 + ty + 16 * i;
        float* dst = g_y + ((size_t)(b * CT + qi)) * CC + h * CD;
#pragma unroll
        for (int j = 0; j < 4; j++)
            dst[tx + 16 * j] = o[i][j] * invl;
    }
}

// ---------------------------------------------------------------------------
extern "C" void kernel_launch(void* const* d_in, const int* in_sizes, int n_in,
                              void* d_out, int out_size) {
    const float* x      = (const float*)d_in[0];
    const float* W_attn = (const float*)d_in[1];
    const float* W_proj = (const float*)d_in[2];
    float* out = (float*)d_out;
    (void)in_sizes; (void)n_in; (void)out_size;

    static bool attrs_set = false;
    if (!attrs_set) {
        cudaFuncSetAttribute(attn_kernel,
                             cudaFuncAttributeMaxDynamicSharedMemorySize, 81920);
        attrs_set = true;
    }

    rope_table_kernel<<<(CT * 32 + 255) / 256, 256>>>();

    {
        dim3 g1(C3 / 128, CM / 128);
        hmma_gemm_kernel<0><<<g1, 512>>>(x, W_attn, nullptr);
    }
    {
        dim3 g2(CT / 128, CB * CH);
        attn_kernel<<<g2, 256, 81920>>>();
    }
    {
        dim3 g3(CC / 128, CM / 128);
        hmma_gemm_kernel<1><<<g3, 512>>>(nullptr, W_proj, out);
    }
}

// round 13
// speedup vs baseline: 1.7000x; 1.3391x over previous
#include <cuda_runtime.h>
#include <cuda_bf16.h>
#include <math.h>
#include <stdint.h>

// Shapes (fixed)
#define CB 4
#define CT 2048
#define CC 1024
#define CH 16
#define CD 64
#define CM (CB*CT)     // 8192
#define C3 (3*CC)      // 3072

// ---------------- device scratch: EXACT R1 set (proven to pass) ------------
__device__ float g_q[(size_t)CB*CH*CT*CD];
__device__ float g_k[(size_t)CB*CH*CT*CD];
__device__ float g_v[(size_t)CB*CH*CT*CD];
__device__ float g_y[(size_t)CM*CC];
__device__ float g_cos[CT*32];
__device__ float g_sin[CT*32];

// ---------------- PTX helpers (compute_100-safe only) -----------------------
__device__ __forceinline__ uint32_t smem_u32(const void* p) {
    uint32_t a;
    asm("{ .reg .u64 t; cvta.to.shared.u64 t, %1; cvt.u32.u64 %0, t; }" : "=r"(a) : "l"(p));
    return a;
}
#define LDSM4(r0,r1,r2,r3,addr) \
    asm volatile("ldmatrix.sync.aligned.m8n8.x4.shared.b16 {%0,%1,%2,%3}, [%4];" \
                 : "=r"(r0), "=r"(r1), "=r"(r2), "=r"(r3) : "r"(addr))
#define MMA16816(d, a0, a1, a2, a3, b0, b1) \
    asm volatile("mma.sync.aligned.m16n8k16.row.col.f32.bf16.bf16.f32 " \
                 "{%0,%1,%2,%3}, {%4,%5,%6,%7}, {%8,%9}, {%0,%1,%2,%3};" \
                 : "+f"((d)[0]), "+f"((d)[1]), "+f"((d)[2]), "+f"((d)[3]) \
                 : "r"(a0), "r"(a1), "r"(a2), "r"(a3), "r"(b0), "r"(b1))

__device__ __forceinline__ uint32_t pack2(float a, float b) {
    __nv_bfloat16 ha = __float2bfloat16_rn(a);
    __nv_bfloat16 hb = __float2bfloat16_rn(b);
    uint16_t ua = *(uint16_t*)&ha, ub = *(uint16_t*)&hb;
    return (uint32_t)ua | ((uint32_t)ub << 16);
}
__device__ __forceinline__ float bf16_val(float v) {
    __nv_bfloat16 h = __float2bfloat16_rn(v);
    return __bfloat162float(h);
}

// Fast exp on FMA pipe: exp(x) = 2^(x*log2e), deg-6 Taylor of 2^f + bit splice.
__device__ __forceinline__ float fexp(float x) {
    float t = fmaxf(x * 1.4426950408889634f, -125.0f);
    float fi = floorf(t);
    float f = t - fi;
    float p = 0.00015403530f;
    p = fmaf(p, f, 0.0013333558f);
    p = fmaf(p, f, 0.0096181291f);
    p = fmaf(p, f, 0.0555041087f);
    p = fmaf(p, f, 0.2402265069f);
    p = fmaf(p, f, 0.6931471806f);
    p = fmaf(p, f, 1.0f);
    return __int_as_float(__float_as_int(p) + (((int)fi) << 23));
}

// ---------------------------------------------------------------------------
// RoPE tables (R1 verbatim)
// ---------------------------------------------------------------------------
__global__ void rope_table_kernel() {
    int idx = blockIdx.x * blockDim.x + threadIdx.x;
    if (idx >= CT * 32) return;
    int t = idx >> 5;
    int i = idx & 31;
    double dinv = pow(10000.0, -(double)(2 * i) / 64.0);
    float invf = (float)dinv;
    float ang = (float)t * invf;
    g_cos[idx] = cosf(ang);
    g_sin[idx] = sinf(ang);
}

// ---------------------------------------------------------------------------
// Split-bf16 HMMA GEMM (R12 verbatim — proven).
// ---------------------------------------------------------------------------
#define LDA 24
#define TILE 3072   // 128*24 elems

template<int MODE>
__global__ __launch_bounds__(512)
void hmma_gemm_kernel(const float* __restrict__ Asrc,
                      const float* __restrict__ Wsrc,
                      float* __restrict__ Out) {
    __shared__ __nv_bfloat16 sm_[8 * TILE];   // 49152 B
    const uint32_t uS = smem_u32(sm_);
    const int N = (MODE == 0) ? C3 : CC;
    const int tid = threadIdx.x;
    const int wid = tid >> 5, lane = tid & 31;
    const int wm = wid >> 2, wn = wid & 3;
    const int m0 = blockIdx.y * 128, n0 = blockIdx.x * 128;
    const float* __restrict__ Ap = (MODE == 0) ? (Asrc + (size_t)m0 * CC)
                                               : (g_y + (size_t)m0 * CC);

    const int arow = tid >> 2;
    const int aq = tid & 3;
    const int wn_ = tid & 127;
    const int wk = tid >> 7;

    float acc[2][4][4];
#pragma unroll
    for (int mi = 0; mi < 2; mi++)
#pragma unroll
        for (int ni = 0; ni < 4; ni++)
#pragma unroll
            for (int r = 0; r < 4; r++) acc[mi][ni][r] = 0.f;

    const int aOff = (wm * 32 + (lane & 15)) * LDA + (lane >> 4) * 8;
    const int bOff = (wn * 32 + ((lane >> 4) & 1) * 8 + (lane & 7)) * LDA
                     + ((lane >> 3) & 1) * 8;

    {
        float4 av = *(const float4*)(Ap + (size_t)arow * CC + aq * 4);
        const float* wp = Wsrc + (size_t)(wk * 4) * N + n0 + wn_;
        float w0 = wp[0], w1 = wp[N], w2 = wp[2 * (size_t)N], w3 = wp[3 * (size_t)N];
        __nv_bfloat16* Ah_ = sm_;
        __nv_bfloat16* Al_ = sm_ + 2 * TILE;
        __nv_bfloat16* Wh_ = sm_ + 4 * TILE;
        __nv_bfloat16* Wl_ = sm_ + 6 * TILE;
        int aoff = arow * LDA + aq * 4;
        *(uint2*)(Ah_ + aoff) = make_uint2(pack2(av.x, av.y), pack2(av.z, av.w));
        *(uint2*)(Al_ + aoff) = make_uint2(
            pack2(av.x - bf16_val(av.x), av.y - bf16_val(av.y)),
            pack2(av.z - bf16_val(av.z), av.w - bf16_val(av.w)));
        int woff = wn_ * LDA + wk * 4;
        *(uint32_t*)(Wh_ + woff)     = pack2(w0, w1);
        *(uint32_t*)(Wh_ + woff + 2) = pack2(w2, w3);
        *(uint32_t*)(Wl_ + woff)     = pack2(w0 - bf16_val(w0), w1 - bf16_val(w1));
        *(uint32_t*)(Wl_ + woff + 2) = pack2(w2 - bf16_val(w2), w3 - bf16_val(w3));
    }
    __syncthreads();

    for (int kc = 0; kc < 64; kc++) {
        const int buf = kc & 1;

        float4 av; float w0, w1, w2, w3;
        if (kc + 1 < 64) {
            av = *(const float4*)(Ap + (size_t)arow * CC + (kc + 1) * 16 + aq * 4);
            const float* wp = Wsrc + (size_t)((kc + 1) * 16 + wk * 4) * N + n0 + wn_;
            w0 = wp[0]; w1 = wp[N]; w2 = wp[2 * (size_t)N]; w3 = wp[3 * (size_t)N];
        }

        const uint32_t bAh = uS + (uint32_t)(buf * TILE) * 2;
        const uint32_t bAl = uS + (uint32_t)(2 * TILE + buf * TILE) * 2;
        const uint32_t bWh = uS + (uint32_t)(4 * TILE + buf * TILE) * 2;
        const uint32_t bWl = uS + (uint32_t)(6 * TILE + buf * TILE) * 2;
        const uint32_t offB0 = (uint32_t)(bOff) * 2;
        const uint32_t offB1 = (uint32_t)(bOff + 16 * LDA) * 2;

        uint32_t wh0, wh1, wh2, wh3, wh4, wh5, wh6, wh7;
        uint32_t wl0, wl1, wl2, wl3, wl4, wl5, wl6, wl7;
        LDSM4(wh0, wh1, wh2, wh3, bWh + offB0);
        LDSM4(wh4, wh5, wh6, wh7, bWh + offB1);
        LDSM4(wl0, wl1, wl2, wl3, bWl + offB0);
        LDSM4(wl4, wl5, wl6, wl7, bWl + offB1);
#pragma unroll
        for (int mi = 0; mi < 2; mi++) {
            uint32_t offA = (uint32_t)(aOff + mi * 16 * LDA) * 2;
            uint32_t a0, a1, a2, a3;
            LDSM4(a0, a1, a2, a3, bAh + offA);
            MMA16816(acc[mi][0], a0, a1, a2, a3, wh0, wh1);
            MMA16816(acc[mi][1], a0, a1, a2, a3, wh2, wh3);
            MMA16816(acc[mi][2], a0, a1, a2, a3, wh4, wh5);
            MMA16816(acc[mi][3], a0, a1, a2, a3, wh6, wh7);
            MMA16816(acc[mi][0], a0, a1, a2, a3, wl0, wl1);
            MMA16816(acc[mi][1], a0, a1, a2, a3, wl2, wl3);
            MMA16816(acc[mi][2], a0, a1, a2, a3, wl4, wl5);
            MMA16816(acc[mi][3], a0, a1, a2, a3, wl6, wl7);
            LDSM4(a0, a1, a2, a3, bAl + offA);
            MMA16816(acc[mi][0], a0, a1, a2, a3, wh0, wh1);
            MMA16816(acc[mi][1], a0, a1, a2, a3, wh2, wh3);
            MMA16816(acc[mi][2], a0, a1, a2, a3, wh4, wh5);
            MMA16816(acc[mi][3], a0, a1, a2, a3, wh6, wh7);
        }

        __syncthreads();

        if (kc + 1 < 64) {
            const int b2 = buf ^ 1;
            __nv_bfloat16* Ah_ = sm_ + b2 * TILE;
            __nv_bfloat16* Al_ = sm_ + 2 * TILE + b2 * TILE;
            __nv_bfloat16* Wh_ = sm_ + 4 * TILE + b2 * TILE;
            __nv_bfloat16* Wl_ = sm_ + 6 * TILE + b2 * TILE;
            int aoff = arow * LDA + aq * 4;
            *(uint2*)(Ah_ + aoff) = make_uint2(pack2(av.x, av.y), pack2(av.z, av.w));
            *(uint2*)(Al_ + aoff) = make_uint2(
                pack2(av.x - bf16_val(av.x), av.y - bf16_val(av.y)),
                pack2(av.z - bf16_val(av.z), av.w - bf16_val(av.w)));
            int woff = wn_ * LDA + wk * 4;
            *(uint32_t*)(Wh_ + woff)     = pack2(w0, w1);
            *(uint32_t*)(Wh_ + woff + 2) = pack2(w2, w3);
            *(uint32_t*)(Wl_ + woff)     = pack2(w0 - bf16_val(w0), w1 - bf16_val(w1));
            *(uint32_t*)(Wl_ + woff + 2) = pack2(w2 - bf16_val(w2), w3 - bf16_val(w3));
            __syncthreads();
        }
    }

    const int lrow = lane >> 2;
    const int lcol = (lane & 3) * 2;

#pragma unroll
    for (int mi = 0; mi < 2; mi++) {
#pragma unroll
        for (int rh = 0; rh < 2; rh++) {
            const int r = m0 + wm * 32 + mi * 16 + lrow + rh * 8;
            if (MODE == 1) {
                float* dst = Out + (size_t)r * CC + n0 + wn * 32 + lcol;
#pragma unroll
                for (int ni = 0; ni < 4; ni++)
                    *(float2*)(dst + ni * 8) =
                        make_float2(acc[mi][ni][2 * rh], acc[mi][ni][2 * rh + 1]);
            } else {
                const int bI = r >> 11, t = r & 2047;
                const float* ct = g_cos + t * 32;
                const float* st = g_sin + t * 32;
#pragma unroll
                for (int ni = 0; ni < 4; ni++) {
                    const int cg = n0 + wn * 32 + ni * 8 + lcol;
                    const int seg = cg >> 10;
                    const int cs = cg & 1023;
                    const int h = cs >> 6, d = cs & 63;
                    float* base = (seg == 0) ? g_q : ((seg == 1) ? g_k : g_v);
                    float* dst = base + (((size_t)(bI * CH + h) * CT + t) * CD + d);
                    float x1 = acc[mi][ni][2 * rh], x2 = acc[mi][ni][2 * rh + 1];
                    if (seg == 2) {
                        *(float2*)dst = make_float2(x1, x2);
                    } else {
                        float c = ct[d >> 1], s = st[d >> 1];
                        *(float2*)dst = make_float2(x1 * c - x2 * s, x1 * s + x2 * c);
                    }
                }
            }
        }
    }
}

// ---------------------------------------------------------------------------
// HMMA flash attention. 256 thr = 8 warps x 16 q-rows, BM=128, BN=64.
// S = (Q/8)·K^T via 3-way bf16 split; P kept in registers (C-frag == A-frag);
// O += Ph·Vh + Pl·Vh + Ph·Vl. exp on FMA pipe (fexp). Writes y fp32 to g_y.
// Smem (elems, ALDA=72): Qh 0 | Ql 9216 | Kh 18432 | Kl 23040 | Vth 27648 |
//                        Vtl 32256 | total 36864 elems = 73728 B dynamic.
// ---------------------------------------------------------------------------
#define ALDA 72

__global__ __launch_bounds__(256)
void attn_hmma_kernel() {
    extern __shared__ __nv_bfloat16 smA[];
    const uint32_t uS = smem_u32(smA);
    const uint32_t uQh = uS;
    const uint32_t uQl = uS + 9216u * 2;
    const uint32_t uKh = uS + 18432u * 2;
    const uint32_t uKl = uS + 23040u * 2;
    const uint32_t uVh = uS + 27648u * 2;
    const uint32_t uVl = uS + 32256u * 2;

    const int tid = threadIdx.x;
    const int wid = tid >> 5, lane = tid & 31;
    const int bh = blockIdx.y;
    const int qb = gridDim.x - 1 - blockIdx.x;
    const int q0 = qb * 128;
    const float* Qg = g_q + (size_t)bh * CT * CD;
    const float* Kg = g_k + (size_t)bh * CT * CD;
    const float* Vg = g_v + (size_t)bh * CT * CD;

    // ---- load Q (scaled by 0.125) split into Qh/Ql ----
#pragma unroll
    for (int i = 0; i < 8; i++) {
        int idx = tid + 256 * i;
        int row = idx >> 4, seg = idx & 15;
        float4 v = *(const float4*)(Qg + (size_t)(q0 + row) * CD + seg * 4);
        v.x *= 0.125f; v.y *= 0.125f; v.z *= 0.125f; v.w *= 0.125f;
        int off = row * ALDA + seg * 4;
        *(uint2*)(smA + off) = make_uint2(pack2(v.x, v.y), pack2(v.z, v.w));
        *(uint2*)(smA + 9216 + off) = make_uint2(
            pack2(v.x - bf16_val(v.x), v.y - bf16_val(v.y)),
            pack2(v.z - bf16_val(v.z), v.w - bf16_val(v.w)));
    }

    float o[8][4], sacc[8][4];
#pragma unroll
    for (int n = 0; n < 8; n++)
#pragma unroll
        for (int v = 0; v < 4; v++) o[n][v] = 0.f;
    float m0r = -3.0e38f, m1r = -3.0e38f, l0r = 0.f, l1r = 0.f;

    // ldmatrix lane offsets (elems)
    const int aOffQ = (wid * 16 + (lane & 15)) * ALDA + (lane >> 4) * 8;
    const int bOffR = ((lane >> 4) & 1) * 8 + (lane & 7);   // row part within 32-group
    const int bOffC = ((lane >> 3) & 1) * 8;                // k-col part

    const int ntiles = 2 * qb + 2;
    for (int nt = 0; nt < ntiles; nt++) {
        const int k0 = nt * 64;
        __syncthreads();   // prior tile's reads of K/V done (and Q written, nt=0)

        // ---- load K tile (64x64) split ----
#pragma unroll
        for (int i = 0; i < 4; i++) {
            int idx = tid + 256 * i;
            int row = idx >> 4, seg = idx & 15;
            float4 v = *(const float4*)(Kg + (size_t)(k0 + row) * CD + seg * 4);
            int off = row * ALDA + seg * 4;
            *(uint2*)(smA + 18432 + off) = make_uint2(pack2(v.x, v.y), pack2(v.z, v.w));
            *(uint2*)(smA + 23040 + off) = make_uint2(
                pack2(v.x - bf16_val(v.x), v.y - bf16_val(v.y)),
                pack2(v.z - bf16_val(v.z), v.w - bf16_val(v.w)));
        }
        // ---- load V tile transposed (Vt[d][kv]) split ----
#pragma unroll
        for (int i = 0; i < 4; i++) {
            int idx = tid + 256 * i;
            int row = idx >> 4, seg = idx & 15;   // row = kv, d = seg*4+j
            float4 v = *(const float4*)(Vg + (size_t)(k0 + row) * CD + seg * 4);
            float vs0 = v.x, vs1 = v.y, vs2 = v.z, vs3 = v.w;
            int d0 = seg * 4;
            smA[27648 + (d0 + 0) * ALDA + row] = __float2bfloat16_rn(vs0);
            smA[27648 + (d0 + 1) * ALDA + row] = __float2bfloat16_rn(vs1);
            smA[27648 + (d0 + 2) * ALDA + row] = __float2bfloat16_rn(vs2);
            smA[27648 + (d0 + 3) * ALDA + row] = __float2bfloat16_rn(vs3);
            smA[32256 + (d0 + 0) * ALDA + row] = __float2bfloat16_rn(vs0 - bf16_val(vs0));
            smA[32256 + (d0 + 1) * ALDA + row] = __float2bfloat16_rn(vs1 - bf16_val(vs1));
            smA[32256 + (d0 + 2) * ALDA + row] = __float2bfloat16_rn(vs2 - bf16_val(vs2));
            smA[32256 + (d0 + 3) * ALDA + row] = __float2bfloat16_rn(vs3 - bf16_val(vs3));
        }
        __syncthreads();

        // ---- S = Qs·K^T (3-way split) ----
#pragma unroll
        for (int n = 0; n < 8; n++)
#pragma unroll
            for (int v = 0; v < 4; v++) sacc[n][v] = 0.f;
#pragma unroll
        for (int ks = 0; ks < 4; ks++) {
            uint32_t offA = (uint32_t)(aOffQ + ks * 16) * 2;
            uint32_t ah0, ah1, ah2, ah3, al0, al1, al2, al3;
            LDSM4(ah0, ah1, ah2, ah3, uQh + offA);
            LDSM4(al0, al1, al2, al3, uQl + offA);
#pragma unroll
            for (int nh = 0; nh < 2; nh++) {
                uint32_t kb = (uint32_t)((nh * 32 + bOffR) * ALDA + ks * 16 + bOffC) * 2;
                uint32_t b0, b1, b2, b3, b4, b5, b6, b7;
                LDSM4(b0, b1, b2, b3, uKh + kb);
                LDSM4(b4, b5, b6, b7, uKh + kb + 16 * ALDA * 2);
                MMA16816(sacc[nh * 4 + 0], ah0, ah1, ah2, ah3, b0, b1);
                MMA16816(sacc[nh * 4 + 1], ah0, ah1, ah2, ah3, b2, b3);
                MMA16816(sacc[nh * 4 + 2], ah0, ah1, ah2, ah3, b4, b5);
                MMA16816(sacc[nh * 4 + 3], ah0, ah1, ah2, ah3, b6, b7);
                MMA16816(sacc[nh * 4 + 0], al0, al1, al2, al3, b0, b1);
                MMA16816(sacc[nh * 4 + 1], al0, al1, al2, al3, b2, b3);
                MMA16816(sacc[nh * 4 + 2], al0, al1, al2, al3, b4, b5);
                MMA16816(sacc[nh * 4 + 3], al0, al1, al2, al3, b6, b7);
                LDSM4(b0, b1, b2, b3, uKl + kb);
                LDSM4(b4, b5, b6, b7, uKl + kb + 16 * ALDA * 2);
                MMA16816(sacc[nh * 4 + 0], ah0, ah1, ah2, ah3, b0, b1);
                MMA16816(sacc[nh * 4 + 1], ah0, ah1, ah2, ah3, b2, b3);
                MMA16816(sacc[nh * 4 + 2], ah0, ah1, ah2, ah3, b4, b5);
                MMA16816(sacc[nh * 4 + 3], ah0, ah1, ah2, ah3, b6, b7);
            }
        }

        // ---- causal mask (diagonal tiles only) ----
        if (nt >= 2 * qb) {
            const int r0 = q0 + wid * 16 + (lane >> 2);
#pragma unroll
            for (int n = 0; n < 8; n++) {
                int colb = k0 + ((n >> 2) << 5) + ((n & 3) << 3) + (lane & 3) * 2;
#pragma unroll
                for (int v = 0; v < 4; v++) {
                    int col = colb + (v & 1);
                    int row = r0 + (v >> 1) * 8;
                    if (col > row) sacc[n][v] = -1.0e30f;
                }
            }
        }

        // ---- online softmax (rows r0 = lane>>2, r1 = r0+8 of this warp) ----
        float rx0 = -3.0e38f, rx1 = -3.0e38f;
#pragma unroll
        for (int n = 0; n < 8; n++) {
            rx0 = fmaxf(rx0, fmaxf(sacc[n][0], sacc[n][1]));
            rx1 = fmaxf(rx1, fmaxf(sacc[n][2], sacc[n][3]));
        }
        rx0 = fmaxf(rx0, __shfl_xor_sync(0xffffffffu, rx0, 1));
        rx0 = fmaxf(rx0, __shfl_xor_sync(0xffffffffu, rx0, 2));
        rx1 = fmaxf(rx1, __shfl_xor_sync(0xffffffffu, rx1, 1));
        rx1 = fmaxf(rx1, __shfl_xor_sync(0xffffffffu, rx1, 2));
        float mn0 = fmaxf(m0r, rx0), mn1 = fmaxf(m1r, rx1);
        float sf0 = fexp(m0r - mn0), sf1 = fexp(m1r - mn1);
        m0r = mn0; m1r = mn1;
        float rs0 = 0.f, rs1 = 0.f;
#pragma unroll
        for (int n = 0; n < 8; n++) {
            float p0 = fexp(sacc[n][0] - mn0);
            float p1 = fexp(sacc[n][1] - mn0);
            float p2 = fexp(sacc[n][2] - mn1);
            float p3 = fexp(sacc[n][3] - mn1);
            sacc[n][0] = p0; sacc[n][1] = p1; sacc[n][2] = p2; sacc[n][3] = p3;
            rs0 += p0 + p1; rs1 += p2 + p3;
            o[n][0] *= sf0; o[n][1] *= sf0; o[n][2] *= sf1; o[n][3] *= sf1;
        }
        rs0 += __shfl_xor_sync(0xffffffffu, rs0, 1);
        rs0 += __shfl_xor_sync(0xffffffffu, rs0, 2);
        rs1 += __shfl_xor_sync(0xffffffffu, rs1, 1);
        rs1 += __shfl_xor_sync(0xffffffffu, rs1, 2);
        l0r = l0r * sf0 + rs0;
        l1r = l1r * sf1 + rs1;

        // ---- O += P·V (P a-frags from sacc; 3-way split) ----
#pragma unroll
        for (int ks = 0; ks < 4; ks++) {
            float p00 = sacc[2 * ks][0],     p01 = sacc[2 * ks][1];
            float p02 = sacc[2 * ks][2],     p03 = sacc[2 * ks][3];
            float p10 = sacc[2 * ks + 1][0], p11 = sacc[2 * ks + 1][1];
            float p12 = sacc[2 * ks + 1][2], p13 = sacc[2 * ks + 1][3];
            uint32_t ah0 = pack2(p00, p01), ah1 = pack2(p02, p03);
            uint32_t ah2 = pack2(p10, p11), ah3 = pack2(p12, p13);
            uint32_t al0 = pack2(p00 - bf16_val(p00), p01 - bf16_val(p01));
            uint32_t al1 = pack2(p02 - bf16_val(p02), p03 - bf16_val(p03));
            uint32_t al2 = pack2(p10 - bf16_val(p10), p11 - bf16_val(p11));
            uint32_t al3 = pack2(p12 - bf16_val(p12), p13 - bf16_val(p13));
#pragma unroll
            for (int nh = 0; nh < 2; nh++) {
                uint32_t vb = (uint32_t)((nh * 32 + bOffR) * ALDA + ks * 16 + bOffC) * 2;
                uint32_t b0, b1, b2, b3, b4, b5, b6, b7;
                LDSM4(b0, b1, b2, b3, uVh + vb);
                LDSM4(b4, b5, b6, b7, uVh + vb + 16 * ALDA * 2);
                MMA16816(o[nh * 4 + 0], ah0, ah1, ah2, ah3, b0, b1);
                MMA16816(o[nh * 4 + 1], ah0, ah1, ah2, ah3, b2, b3);
                MMA16816(o[nh * 4 + 2], ah0, ah1, ah2, ah3, b4, b5);
                MMA16816(o[nh * 4 + 3], ah0, ah1, ah2, ah3, b6, b7);
                MMA16816(o[nh * 4 + 0], al0, al1, al2, al3, b0, b1);
                MMA16816(o[nh * 4 + 1], al0, al1, al2, al3, b2, b3);
                MMA16816(o[nh * 4 + 2], al0, al1, al2, al3, b4, b5);
                MMA16816(o[nh * 4 + 3], al0, al1, al2, al3, b6, b7);
                LDSM4(b0, b1, b2, b3, uVl + vb);
                LDSM4(b4, b5, b6, b7, uVl + vb + 16 * ALDA * 2);
                MMA16816(o[nh * 4 + 0], ah0, ah1, ah2, ah3, b0, b1);
                MMA16816(o[nh * 4 + 1], ah0, ah1, ah2, ah3, b2, b3);
                MMA16816(o[nh * 4 + 2], ah0, ah1, ah2, ah3, b4, b5);
                MMA16816(o[nh * 4 + 3], ah0, ah1, ah2, ah3, b6, b7);
            }
        }
    }

    // ---- write y = O / l to g_y [B,T,C] ----
    const int bI = bh >> 4, h = bh & 15;
    const float inv0 = 1.f / l0r, inv1 = 1.f / l1r;
    const int row0 = q0 + wid * 16 + (lane >> 2);
#pragma unroll
    for (int rh = 0; rh < 2; rh++) {
        int row = row0 + rh * 8;
        float invl = rh ? inv1 : inv0;
        float* dst = g_y + ((size_t)(bI * CT + row)) * CC + h * CD + (lane & 3) * 2;
#pragma unroll
        for (int n = 0; n < 8; n++) {
            int d = ((n >> 2) << 5) + ((n & 3) << 3);
            *(float2*)(dst + d) = make_float2(o[n][2 * rh] * invl, o[n][2 * rh + 1] * invl);
        }
    }
}

// ---------------------------------------------------------------------------
extern "C" void kernel_launch(void* const* d_in, const int* in_sizes, int n_in,
                              void* d_out, int out_size) {
    const float* x      = (const float*)d_in[0];
    const float* W_attn = (const float*)d_in[1];
    const float* W_proj = (const float*)d_in[2];
    float* out = (float*)d_out;
    (void)in_sizes; (void)n_in; (void)out_size;

    static bool attrs_set = false;
    if (!attrs_set) {
        cudaFuncSetAttribute(attn_hmma_kernel,
                             cudaFuncAttributeMaxDynamicSharedMemorySize, 73728);
        attrs_set = true;
    }

    rope_table_kernel<<<(CT * 32 + 255) / 256, 256>>>();

    {
        dim3 g1(C3 / 128, CM / 128);
        hmma_gemm_kernel<0><<<g1, 512>>>(x, W_attn, nullptr);
    }
    {
        dim3 g2(CT / 128, CB * CH);
        attn_hmma_kernel<<<g2, 256, 73728>>>();
    }
    {
        dim3 g3(CC / 128, CM / 128);
        hmma_gemm_kernel<1><<<g3, 512>>>(nullptr, W_proj, out);
    }
}

// round 14
// speedup vs baseline: 1.9528x; 1.1488x over previous
#include <cuda_runtime.h>
#include <cuda_bf16.h>
#include <math.h>
#include <stdint.h>

// Shapes (fixed)
#define CB 4
#define CT 2048
#define CC 1024
#define CH 16
#define CD 64
#define CM (CB*CT)     // 8192
#define C3 (3*CC)      // 3072

// ---------------- device scratch: EXACT R1 set (proven to pass) ------------
__device__ float g_q[(size_t)CB*CH*CT*CD];
__device__ float g_k[(size_t)CB*CH*CT*CD];
__device__ float g_v[(size_t)CB*CH*CT*CD];
__device__ float g_y[(size_t)CM*CC];
__device__ float g_cos[CT*32];
__device__ float g_sin[CT*32];

// ---------------- PTX helpers (compute_100-safe only) -----------------------
__device__ __forceinline__ uint32_t smem_u32(const void* p) {
    uint32_t a;
    asm("{ .reg .u64 t; cvta.to.shared.u64 t, %1; cvt.u32.u64 %0, t; }" : "=r"(a) : "l"(p));
    return a;
}
#define LDSM4(r0,r1,r2,r3,addr) \
    asm volatile("ldmatrix.sync.aligned.m8n8.x4.shared.b16 {%0,%1,%2,%3}, [%4];" \
                 : "=r"(r0), "=r"(r1), "=r"(r2), "=r"(r3) : "r"(addr))
#define MMA16816(d, a0, a1, a2, a3, b0, b1) \
    asm volatile("mma.sync.aligned.m16n8k16.row.col.f32.bf16.bf16.f32 " \
                 "{%0,%1,%2,%3}, {%4,%5,%6,%7}, {%8,%9}, {%0,%1,%2,%3};" \
                 : "+f"((d)[0]), "+f"((d)[1]), "+f"((d)[2]), "+f"((d)[3]) \
                 : "r"(a0), "r"(a1), "r"(a2), "r"(a3), "r"(b0), "r"(b1))

__device__ __forceinline__ uint32_t pack2(float a, float b) {
    __nv_bfloat16 ha = __float2bfloat16_rn(a);
    __nv_bfloat16 hb = __float2bfloat16_rn(b);
    uint16_t ua = *(uint16_t*)&ha, ub = *(uint16_t*)&hb;
    return (uint32_t)ua | ((uint32_t)ub << 16);
}
__device__ __forceinline__ float bf16_val(float v) {
    __nv_bfloat16 h = __float2bfloat16_rn(v);
    return __bfloat162float(h);
}

// Fast exp on FMA pipe: exp(x) = 2^(x*log2e), deg-6 poly of 2^f + bit splice.
__device__ __forceinline__ float fexp(float x) {
    float t = fmaxf(x * 1.4426950408889634f, -125.0f);
    float fi = floorf(t);
    float f = t - fi;
    float p = 0.00015403530f;
    p = fmaf(p, f, 0.0013333558f);
    p = fmaf(p, f, 0.0096181291f);
    p = fmaf(p, f, 0.0555041087f);
    p = fmaf(p, f, 0.2402265069f);
    p = fmaf(p, f, 0.6931471806f);
    p = fmaf(p, f, 1.0f);
    return __int_as_float(__float_as_int(p) + (((int)fi) << 23));
}

// ---------------------------------------------------------------------------
__global__ void rope_table_kernel() {
    int idx = blockIdx.x * blockDim.x + threadIdx.x;
    if (idx >= CT * 32) return;
    int t = idx >> 5;
    int i = idx & 31;
    double dinv = pow(10000.0, -(double)(2 * i) / 64.0);
    float invf = (float)dinv;
    float ang = (float)t * invf;
    g_cos[idx] = cosf(ang);
    g_sin[idx] = sinf(ang);
}

// ---------------------------------------------------------------------------
// Split-bf16 HMMA GEMM v2: BK=32, dynamic smem 80KB, ONE sync per iteration.
// C = Ah.Wh^T + Ah.Wl^T + Al.Wh^T over K=1024 (32 chunks of 32).
// 128x128 block, 512 threads = 16 warps (4x4), warp tile 32x32 (acc=32 regs).
// Smem elem offsets (LDA=40): Ah buf*5120 | Al 10240+ | Wh 20480+ | Wl 30720+
// No cp.async, no bf16 globals (memory-guard-safe building blocks only).
// MODE 0: qkv (A=x) -> RoPE + scatter;  MODE 1: proj (A=g_y) -> Out.
// ---------------------------------------------------------------------------
#define LDA 40

template<int MODE>
__global__ __launch_bounds__(512)
void hmma_gemm_kernel(const float* __restrict__ Asrc,
                      const float* __restrict__ Wsrc,
                      float* __restrict__ Out) {
    extern __shared__ __nv_bfloat16 sm_[];
    const uint32_t uS = smem_u32(sm_);
    const int N = (MODE == 0) ? C3 : CC;
    const int tid = threadIdx.x;
    const int wid = tid >> 5, lane = tid & 31;
    const int wm = wid >> 2, wn = wid & 3;          // 4x4 warp grid
    const int m0 = blockIdx.y * 128, n0 = blockIdx.x * 128;
    const float* __restrict__ Ap = (MODE == 0) ? (Asrc + (size_t)m0 * CC)
                                               : (g_y + (size_t)m0 * CC);

    // A staging: row ar (0..127), 8-float segment as (0..3)
    const int ar = tid >> 2;
    const int as = tid & 3;
    // W staging: col wn_ (0..127), 8-k group wk (0..3)
    const int wn_ = tid & 127;
    const int wk = tid >> 7;

    float acc[2][4][4];
#pragma unroll
    for (int mi = 0; mi < 2; mi++)
#pragma unroll
        for (int ni = 0; ni < 4; ni++)
#pragma unroll
            for (int r = 0; r < 4; r++) acc[mi][ni][r] = 0.f;

    const int aOff = (wm * 32 + (lane & 15)) * LDA + (lane >> 4) * 8;
    const int bOff = (wn * 32 + ((lane >> 4) & 1) * 8 + (lane & 7)) * LDA
                     + ((lane >> 3) & 1) * 8;

    // ---- stage chunk 0 into buffer 0 ----
    {
        float4 a0 = *(const float4*)(Ap + (size_t)ar * CC + as * 8);
        float4 a1 = *(const float4*)(Ap + (size_t)ar * CC + as * 8 + 4);
        const float* wp = Wsrc + (size_t)(wk * 8) * N + n0 + wn_;
        float w0 = wp[0], w1 = wp[N], w2 = wp[2*(size_t)N], w3 = wp[3*(size_t)N];
        float w4 = wp[4*(size_t)N], w5 = wp[5*(size_t)N], w6 = wp[6*(size_t)N], w7 = wp[7*(size_t)N];
        int aoff = ar * LDA + as * 8;
        *(uint2*)(sm_ + aoff) = make_uint2(pack2(a0.x, a0.y), pack2(a0.z, a0.w));
        *(uint2*)(sm_ + aoff + 4) = make_uint2(pack2(a1.x, a1.y), pack2(a1.z, a1.w));
        *(uint2*)(sm_ + 10240 + aoff) = make_uint2(
            pack2(a0.x - bf16_val(a0.x), a0.y - bf16_val(a0.y)),
            pack2(a0.z - bf16_val(a0.z), a0.w - bf16_val(a0.w)));
        *(uint2*)(sm_ + 10240 + aoff + 4) = make_uint2(
            pack2(a1.x - bf16_val(a1.x), a1.y - bf16_val(a1.y)),
            pack2(a1.z - bf16_val(a1.z), a1.w - bf16_val(a1.w)));
        int woff = wn_ * LDA + wk * 8;
        *(uint32_t*)(sm_ + 20480 + woff)     = pack2(w0, w1);
        *(uint32_t*)(sm_ + 20480 + woff + 2) = pack2(w2, w3);
        *(uint32_t*)(sm_ + 20480 + woff + 4) = pack2(w4, w5);
        *(uint32_t*)(sm_ + 20480 + woff + 6) = pack2(w6, w7);
        *(uint32_t*)(sm_ + 30720 + woff)     = pack2(w0 - bf16_val(w0), w1 - bf16_val(w1));
        *(uint32_t*)(sm_ + 30720 + woff + 2) = pack2(w2 - bf16_val(w2), w3 - bf16_val(w3));
        *(uint32_t*)(sm_ + 30720 + woff + 4) = pack2(w4 - bf16_val(w4), w5 - bf16_val(w5));
        *(uint32_t*)(sm_ + 30720 + woff + 6) = pack2(w6 - bf16_val(w6), w7 - bf16_val(w7));
    }
    __syncthreads();

    for (int kc = 0; kc < 32; kc++) {
        const int buf = kc & 1;

        // prefetch next chunk's globals into registers
        float4 a0, a1;
        float w0, w1, w2, w3, w4, w5, w6, w7;
        if (kc + 1 < 32) {
            a0 = *(const float4*)(Ap + (size_t)ar * CC + (kc + 1) * 32 + as * 8);
            a1 = *(const float4*)(Ap + (size_t)ar * CC + (kc + 1) * 32 + as * 8 + 4);
            const float* wp = Wsrc + (size_t)((kc + 1) * 32 + wk * 8) * N + n0 + wn_;
            w0 = wp[0]; w1 = wp[N]; w2 = wp[2*(size_t)N]; w3 = wp[3*(size_t)N];
            w4 = wp[4*(size_t)N]; w5 = wp[5*(size_t)N]; w6 = wp[6*(size_t)N]; w7 = wp[7*(size_t)N];
        }

        // ---- compute on buf ----
        const uint32_t bAh = uS + (uint32_t)(buf * 5120) * 2;
        const uint32_t bAl = uS + (uint32_t)(10240 + buf * 5120) * 2;
        const uint32_t bWh = uS + (uint32_t)(20480 + buf * 5120) * 2;
        const uint32_t bWl = uS + (uint32_t)(30720 + buf * 5120) * 2;

#pragma unroll
        for (int ks = 0; ks < 2; ks++) {
            const uint32_t offB0 = (uint32_t)(bOff + ks * 16) * 2;
            const uint32_t offB1 = (uint32_t)(bOff + ks * 16 + 16 * LDA) * 2;
            uint32_t wh0, wh1, wh2, wh3, wh4, wh5, wh6, wh7;
            uint32_t wl0, wl1, wl2, wl3, wl4, wl5, wl6, wl7;
            LDSM4(wh0, wh1, wh2, wh3, bWh + offB0);
            LDSM4(wh4, wh5, wh6, wh7, bWh + offB1);
            LDSM4(wl0, wl1, wl2, wl3, bWl + offB0);
            LDSM4(wl4, wl5, wl6, wl7, bWl + offB1);
#pragma unroll
            for (int mi = 0; mi < 2; mi++) {
                uint32_t offA = (uint32_t)(aOff + ks * 16 + mi * 16 * LDA) * 2;
                uint32_t x0, x1, x2, x3;
                LDSM4(x0, x1, x2, x3, bAh + offA);
                MMA16816(acc[mi][0], x0, x1, x2, x3, wh0, wh1);
                MMA16816(acc[mi][1], x0, x1, x2, x3, wh2, wh3);
                MMA16816(acc[mi][2], x0, x1, x2, x3, wh4, wh5);
                MMA16816(acc[mi][3], x0, x1, x2, x3, wh6, wh7);
                MMA16816(acc[mi][0], x0, x1, x2, x3, wl0, wl1);
                MMA16816(acc[mi][1], x0, x1, x2, x3, wl2, wl3);
                MMA16816(acc[mi][2], x0, x1, x2, x3, wl4, wl5);
                MMA16816(acc[mi][3], x0, x1, x2, x3, wl6, wl7);
                LDSM4(x0, x1, x2, x3, bAl + offA);
                MMA16816(acc[mi][0], x0, x1, x2, x3, wh0, wh1);
                MMA16816(acc[mi][1], x0, x1, x2, x3, wh2, wh3);
                MMA16816(acc[mi][2], x0, x1, x2, x3, wh4, wh5);
                MMA16816(acc[mi][3], x0, x1, x2, x3, wh6, wh7);
            }
        }

        // ---- stage next chunk into buf^1 (disjoint from compute buf) ----
        if (kc + 1 < 32) {
            const int b2 = buf ^ 1;
            __nv_bfloat16* Ah_ = sm_ + b2 * 5120;
            __nv_bfloat16* Al_ = sm_ + 10240 + b2 * 5120;
            __nv_bfloat16* Wh_ = sm_ + 20480 + b2 * 5120;
            __nv_bfloat16* Wl_ = sm_ + 30720 + b2 * 5120;
            int aoff = ar * LDA + as * 8;
            *(uint2*)(Ah_ + aoff) = make_uint2(pack2(a0.x, a0.y), pack2(a0.z, a0.w));
            *(uint2*)(Ah_ + aoff + 4) = make_uint2(pack2(a1.x, a1.y), pack2(a1.z, a1.w));
            *(uint2*)(Al_ + aoff) = make_uint2(
                pack2(a0.x - bf16_val(a0.x), a0.y - bf16_val(a0.y)),
                pack2(a0.z - bf16_val(a0.z), a0.w - bf16_val(a0.w)));
            *(uint2*)(Al_ + aoff + 4) = make_uint2(
                pack2(a1.x - bf16_val(a1.x), a1.y - bf16_val(a1.y)),
                pack2(a1.z - bf16_val(a1.z), a1.w - bf16_val(a1.w)));
            int woff = wn_ * LDA + wk * 8;
            *(uint32_t*)(Wh_ + woff)     = pack2(w0, w1);
            *(uint32_t*)(Wh_ + woff + 2) = pack2(w2, w3);
            *(uint32_t*)(Wh_ + woff + 4) = pack2(w4, w5);
            *(uint32_t*)(Wh_ + woff + 6) = pack2(w6, w7);
            *(uint32_t*)(Wl_ + woff)     = pack2(w0 - bf16_val(w0), w1 - bf16_val(w1));
            *(uint32_t*)(Wl_ + woff + 2) = pack2(w2 - bf16_val(w2), w3 - bf16_val(w3));
            *(uint32_t*)(Wl_ + woff + 4) = pack2(w4 - bf16_val(w4), w5 - bf16_val(w5));
            *(uint32_t*)(Wl_ + woff + 6) = pack2(w6 - bf16_val(w6), w7 - bf16_val(w7));
        }
        __syncthreads();   // publishes staged buf^1; protects buf until next overwrite
    }

    // ------------- epilogue --------------------------------------------------
    const int lrow = lane >> 2;
    const int lcol = (lane & 3) * 2;

#pragma unroll
    for (int mi = 0; mi < 2; mi++) {
#pragma unroll
        for (int rh = 0; rh < 2; rh++) {
            const int r = m0 + wm * 32 + mi * 16 + lrow + rh * 8;
            if (MODE == 1) {
                float* dst = Out + (size_t)r * CC + n0 + wn * 32 + lcol;
#pragma unroll
                for (int ni = 0; ni < 4; ni++)
                    *(float2*)(dst + ni * 8) =
                        make_float2(acc[mi][ni][2 * rh], acc[mi][ni][2 * rh + 1]);
            } else {
                const int bI = r >> 11, t = r & 2047;
                const float* ct = g_cos + t * 32;
                const float* st = g_sin + t * 32;
#pragma unroll
                for (int ni = 0; ni < 4; ni++) {
                    const int cg = n0 + wn * 32 + ni * 8 + lcol;
                    const int seg = cg >> 10;
                    const int cs = cg & 1023;
                    const int h = cs >> 6, d = cs & 63;
                    float* base = (seg == 0) ? g_q : ((seg == 1) ? g_k : g_v);
                    float* dst = base + (((size_t)(bI * CH + h) * CT + t) * CD + d);
                    float x1 = acc[mi][ni][2 * rh], x2 = acc[mi][ni][2 * rh + 1];
                    if (seg == 2) {
                        *(float2*)dst = make_float2(x1, x2);
                    } else {
                        float c = ct[d >> 1], s = st[d >> 1];
                        *(float2*)dst = make_float2(x1 * c - x2 * s, x1 * s + x2 * c);
                    }
                }
            }
        }
    }
}

// ---------------------------------------------------------------------------
// HMMA flash attention (R13 verbatim — proven). Writes y fp32 to g_y.
// ---------------------------------------------------------------------------
#define ALDA 72

__global__ __launch_bounds__(256)
void attn_hmma_kernel() {
    extern __shared__ __nv_bfloat16 smA[];
    const uint32_t uS = smem_u32(smA);
    const uint32_t uQh = uS;
    const uint32_t uQl = uS + 9216u * 2;
    const uint32_t uKh = uS + 18432u * 2;
    const uint32_t uKl = uS + 23040u * 2;
    const uint32_t uVh = uS + 27648u * 2;
    const uint32_t uVl = uS + 32256u * 2;

    const int tid = threadIdx.x;
    const int wid = tid >> 5, lane = tid & 31;
    const int bh = blockIdx.y;
    const int qb = gridDim.x - 1 - blockIdx.x;
    const int q0 = qb * 128;
    const float* Qg = g_q + (size_t)bh * CT * CD;
    const float* Kg = g_k + (size_t)bh * CT * CD;
    const float* Vg = g_v + (size_t)bh * CT * CD;

#pragma unroll
    for (int i = 0; i < 8; i++) {
        int idx = tid + 256 * i;
        int row = idx >> 4, seg = idx & 15;
        float4 v = *(const float4*)(Qg + (size_t)(q0 + row) * CD + seg * 4);
        v.x *= 0.125f; v.y *= 0.125f; v.z *= 0.125f; v.w *= 0.125f;
        int off = row * ALDA + seg * 4;
        *(uint2*)(smA + off) = make_uint2(pack2(v.x, v.y), pack2(v.z, v.w));
        *(uint2*)(smA + 9216 + off) = make_uint2(
            pack2(v.x - bf16_val(v.x), v.y - bf16_val(v.y)),
            pack2(v.z - bf16_val(v.z), v.w - bf16_val(v.w)));
    }

    float o[8][4], sacc[8][4];
#pragma unroll
    for (int n = 0; n < 8; n++)
#pragma unroll
        for (int v = 0; v < 4; v++) o[n][v] = 0.f;
    float m0r = -3.0e38f, m1r = -3.0e38f, l0r = 0.f, l1r = 0.f;

    const int aOffQ = (wid * 16 + (lane & 15)) * ALDA + (lane >> 4) * 8;
    const int bOffR = ((lane >> 4) & 1) * 8 + (lane & 7);
    const int bOffC = ((lane >> 3) & 1) * 8;

    const int ntiles = 2 * qb + 2;
    for (int nt = 0; nt < ntiles; nt++) {
        const int k0 = nt * 64;
        __syncthreads();

#pragma unroll
        for (int i = 0; i < 4; i++) {
            int idx = tid + 256 * i;
            int row = idx >> 4, seg = idx & 15;
            float4 v = *(const float4*)(Kg + (size_t)(k0 + row) * CD + seg * 4);
            int off = row * ALDA + seg * 4;
            *(uint2*)(smA + 18432 + off) = make_uint2(pack2(v.x, v.y), pack2(v.z, v.w));
            *(uint2*)(smA + 23040 + off) = make_uint2(
                pack2(v.x - bf16_val(v.x), v.y - bf16_val(v.y)),
                pack2(v.z - bf16_val(v.z), v.w - bf16_val(v.w)));
        }
#pragma unroll
        for (int i = 0; i < 4; i++) {
            int idx = tid + 256 * i;
            int row = idx >> 4, seg = idx & 15;
            float4 v = *(const float4*)(Vg + (size_t)(k0 + row) * CD + seg * 4);
            float vs0 = v.x, vs1 = v.y, vs2 = v.z, vs3 = v.w;
            int d0 = seg * 4;
            smA[27648 + (d0 + 0) * ALDA + row] = __float2bfloat16_rn(vs0);
            smA[27648 + (d0 + 1) * ALDA + row] = __float2bfloat16_rn(vs1);
            smA[27648 + (d0 + 2) * ALDA + row] = __float2bfloat16_rn(vs2);
            smA[27648 + (d0 + 3) * ALDA + row] = __float2bfloat16_rn(vs3);
            smA[32256 + (d0 + 0) * ALDA + row] = __float2bfloat16_rn(vs0 - bf16_val(vs0));
            smA[32256 + (d0 + 1) * ALDA + row] = __float2bfloat16_rn(vs1 - bf16_val(vs1));
            smA[32256 + (d0 + 2) * ALDA + row] = __float2bfloat16_rn(vs2 - bf16_val(vs2));
            smA[32256 + (d0 + 3) * ALDA + row] = __float2bfloat16_rn(vs3 - bf16_val(vs3));
        }
        __syncthreads();

#pragma unroll
        for (int n = 0; n < 8; n++)
#pragma unroll
            for (int v = 0; v < 4; v++) sacc[n][v] = 0.f;
#pragma unroll
        for (int ks = 0; ks < 4; ks++) {
            uint32_t offA = (uint32_t)(aOffQ + ks * 16) * 2;
            uint32_t ah0, ah1, ah2, ah3, al0, al1, al2, al3;
            LDSM4(ah0, ah1, ah2, ah3, uQh + offA);
            LDSM4(al0, al1, al2, al3, uQl + offA);
#pragma unroll
            for (int nh = 0; nh < 2; nh++) {
                uint32_t kb = (uint32_t)((nh * 32 + bOffR) * ALDA + ks * 16 + bOffC) * 2;
                uint32_t b0, b1, b2, b3, b4, b5, b6, b7;
                LDSM4(b0, b1, b2, b3, uKh + kb);
                LDSM4(b4, b5, b6, b7, uKh + kb + 16 * ALDA * 2);
                MMA16816(sacc[nh * 4 + 0], ah0, ah1, ah2, ah3, b0, b1);
                MMA16816(sacc[nh * 4 + 1], ah0, ah1, ah2, ah3, b2, b3);
                MMA16816(sacc[nh * 4 + 2], ah0, ah1, ah2, ah3, b4, b5);
                MMA16816(sacc[nh * 4 + 3], ah0, ah1, ah2, ah3, b6, b7);
                MMA16816(sacc[nh * 4 + 0], al0, al1, al2, al3, b0, b1);
                MMA16816(sacc[nh * 4 + 1], al0, al1, al2, al3, b2, b3);
                MMA16816(sacc[nh * 4 + 2], al0, al1, al2, al3, b4, b5);
                MMA16816(sacc[nh * 4 + 3], al0, al1, al2, al3, b6, b7);
                LDSM4(b0, b1, b2, b3, uKl + kb);
                LDSM4(b4, b5, b6, b7, uKl + kb + 16 * ALDA * 2);
                MMA16816(sacc[nh * 4 + 0], ah0, ah1, ah2, ah3, b0, b1);
                MMA16816(sacc[nh * 4 + 1], ah0, ah1, ah2, ah3, b2, b3);
                MMA16816(sacc[nh * 4 + 2], ah0, ah1, ah2, ah3, b4, b5);
                MMA16816(sacc[nh * 4 + 3], ah0, ah1, ah2, ah3, b6, b7);
            }
        }

        if (nt >= 2 * qb) {
            const int r0 = q0 + wid * 16 + (lane >> 2);
#pragma unroll
            for (int n = 0; n < 8; n++) {
                int colb = k0 + ((n >> 2) << 5) + ((n & 3) << 3) + (lane & 3) * 2;
#pragma unroll
                for (int v = 0; v < 4; v++) {
                    int col = colb + (v & 1);
                    int row = r0 + (v >> 1) * 8;
                    if (col > row) sacc[n][v] = -1.0e30f;
                }
            }
        }

        float rx0 = -3.0e38f, rx1 = -3.0e38f;
#pragma unroll
        for (int n = 0; n < 8; n++) {
            rx0 = fmaxf(rx0, fmaxf(sacc[n][0], sacc[n][1]));
            rx1 = fmaxf(rx1, fmaxf(sacc[n][2], sacc[n][3]));
        }
        rx0 = fmaxf(rx0, __shfl_xor_sync(0xffffffffu, rx0, 1));
        rx0 = fmaxf(rx0, __shfl_xor_sync(0xffffffffu, rx0, 2));
        rx1 = fmaxf(rx1, __shfl_xor_sync(0xffffffffu, rx1, 1));
        rx1 = fmaxf(rx1, __shfl_xor_sync(0xffffffffu, rx1, 2));
        float mn0 = fmaxf(m0r, rx0), mn1 = fmaxf(m1r, rx1);
        float sf0 = fexp(m0r - mn0), sf1 = fexp(m1r - mn1);
        m0r = mn0; m1r = mn1;
        float rs0 = 0.f, rs1 = 0.f;
#pragma unroll
        for (int n = 0; n < 8; n++) {
            float p0 = fexp(sacc[n][0] - mn0);
            float p1 = fexp(sacc[n][1] - mn0);
            float p2 = fexp(sacc[n][2] - mn1);
            float p3 = fexp(sacc[n][3] - mn1);
            sacc[n][0] = p0; sacc[n][1] = p1; sacc[n][2] = p2; sacc[n][3] = p3;
            rs0 += p0 + p1; rs1 += p2 + p3;
            o[n][0] *= sf0; o[n][1] *= sf0; o[n][2] *= sf1; o[n][3] *= sf1;
        }
        rs0 += __shfl_xor_sync(0xffffffffu, rs0, 1);
        rs0 += __shfl_xor_sync(0xffffffffu, rs0, 2);
        rs1 += __shfl_xor_sync(0xffffffffu, rs1, 1);
        rs1 += __shfl_xor_sync(0xffffffffu, rs1, 2);
        l0r = l0r * sf0 + rs0;
        l1r = l1r * sf1 + rs1;

#pragma unroll
        for (int ks = 0; ks < 4; ks++) {
            float p00 = sacc[2 * ks][0],     p01 = sacc[2 * ks][1];
            float p02 = sacc[2 * ks][2],     p03 = sacc[2 * ks][3];
            float p10 = sacc[2 * ks + 1][0], p11 = sacc[2 * ks + 1][1];
            float p12 = sacc[2 * ks + 1][2], p13 = sacc[2 * ks + 1][3];
            uint32_t ah0 = pack2(p00, p01), ah1 = pack2(p02, p03);
            uint32_t ah2 = pack2(p10, p11), ah3 = pack2(p12, p13);
            uint32_t al0 = pack2(p00 - bf16_val(p00), p01 - bf16_val(p01));
            uint32_t al1 = pack2(p02 - bf16_val(p02), p03 - bf16_val(p03));
            uint32_t al2 = pack2(p10 - bf16_val(p10), p11 - bf16_val(p11));
            uint32_t al3 = pack2(p12 - bf16_val(p12), p13 - bf16_val(p13));
#pragma unroll
            for (int nh = 0; nh < 2; nh++) {
                uint32_t vb = (uint32_t)((nh * 32 + bOffR) * ALDA + ks * 16 + bOffC) * 2;
                uint32_t b0, b1, b2, b3, b4, b5, b6, b7;
                LDSM4(b0, b1, b2, b3, uVh + vb);
                LDSM4(b4, b5, b6, b7, uVh + vb + 16 * ALDA * 2);
                MMA16816(o[nh * 4 + 0], ah0, ah1, ah2, ah3, b0, b1);
                MMA16816(o[nh * 4 + 1], ah0, ah1, ah2, ah3, b2, b3);
                MMA16816(o[nh * 4 + 2], ah0, ah1, ah2, ah3, b4, b5);
                MMA16816(o[nh * 4 + 3], ah0, ah1, ah2, ah3, b6, b7);
                MMA16816(o[nh * 4 + 0], al0, al1, al2, al3, b0, b1);
                MMA16816(o[nh * 4 + 1], al0, al1, al2, al3, b2, b3);
                MMA16816(o[nh * 4 + 2], al0, al1, al2, al3, b4, b5);
                MMA16816(o[nh * 4 + 3], al0, al1, al2, al3, b6, b7);
                LDSM4(b0, b1, b2, b3, uVl + vb);
                LDSM4(b4, b5, b6, b7, uVl + vb + 16 * ALDA * 2);
                MMA16816(o[nh * 4 + 0], ah0, ah1, ah2, ah3, b0, b1);
                MMA16816(o[nh * 4 + 1], ah0, ah1, ah2, ah3, b2, b3);
                MMA16816(o[nh * 4 + 2], ah0, ah1, ah2, ah3, b4, b5);
                MMA16816(o[nh * 4 + 3], ah0, ah1, ah2, ah3, b6, b7);
            }
        }
    }

    const int bI = bh >> 4, h = bh & 15;
    const float inv0 = 1.f / l0r, inv1 = 1.f / l1r;
    const int row0 = q0 + wid * 16 + (lane >> 2);
#pragma unroll
    for (int rh = 0; rh < 2; rh++) {
        int row = row0 + rh * 8;
        float invl = rh ? inv1 : inv0;
        float* dst = g_y + ((size_t)(bI * CT + row)) * CC + h * CD + (lane & 3) * 2;
#pragma unroll
        for (int n = 0; n < 8; n++) {
            int d = ((n >> 2) << 5) + ((n & 3) << 3);
            *(float2*)(dst + d) = make_float2(o[n][2 * rh] * invl, o[n][2 * rh + 1] * invl);
        }
    }
}

// ---------------------------------------------------------------------------
extern "C" void kernel_launch(void* const* d_in, const int* in_sizes, int n_in,
                              void* d_out, int out_size) {
    const float* x      = (const float*)d_in[0];
    const float* W_attn = (const float*)d_in[1];
    const float* W_proj = (const float*)d_in[2];
    float* out = (float*)d_out;
    (void)in_sizes; (void)n_in; (void)out_size;

    static bool attrs_set = false;
    if (!attrs_set) {
        cudaFuncSetAttribute(attn_hmma_kernel,
                             cudaFuncAttributeMaxDynamicSharedMemorySize, 73728);
        cudaFuncSetAttribute(hmma_gemm_kernel<0>,
                             cudaFuncAttributeMaxDynamicSharedMemorySize, 81920);
        cudaFuncSetAttribute(hmma_gemm_kernel<1>,
                             cudaFuncAttributeMaxDynamicSharedMemorySize, 81920);
        attrs_set = true;
    }

    rope_table_kernel<<<(CT * 32 + 255) / 256, 256>>>();

    {
        dim3 g1(C3 / 128, CM / 128);
        hmma_gemm_kernel<0><<<g1, 512, 81920>>>(x, W_attn, nullptr);
    }
    {
        dim3 g2(CT / 128, CB * CH);
        attn_hmma_kernel<<<g2, 256, 73728>>>();
    }
    {
        dim3 g3(CC / 128, CM / 128);
        hmma_gemm_kernel<1><<<g3, 512, 81920>>>(nullptr, W_proj, out);
    }
}

// round 15
// speedup vs baseline: 2.2234x; 1.1386x over previous
#include <cuda_runtime.h>
#include <cuda_bf16.h>
#include <math.h>
#include <stdint.h>

// Shapes (fixed)
#define CB 4
#define CT 2048
#define CC 1024
#define CH 16
#define CD 64
#define CM (CB*CT)     // 8192
#define C3 (3*CC)      // 3072

// ---------------- device scratch: EXACT R1 set (proven to pass) ------------
__device__ float g_q[(size_t)CB*CH*CT*CD];
__device__ float g_k[(size_t)CB*CH*CT*CD];
__device__ float g_v[(size_t)CB*CH*CT*CD];
__device__ float g_y[(size_t)CM*CC];
__device__ float g_cos[CT*32];
__device__ float g_sin[CT*32];

// ---------------- PTX helpers (compute_100-safe only) -----------------------
__device__ __forceinline__ uint32_t smem_u32(const void* p) {
    uint32_t a;
    asm("{ .reg .u64 t; cvta.to.shared.u64 t, %1; cvt.u32.u64 %0, t; }" : "=r"(a) : "l"(p));
    return a;
}
#define LDSM4(r0,r1,r2,r3,addr) \
    asm volatile("ldmatrix.sync.aligned.m8n8.x4.shared.b16 {%0,%1,%2,%3}, [%4];" \
                 : "=r"(r0), "=r"(r1), "=r"(r2), "=r"(r3) : "r"(addr))
#define LDSM4T(r0,r1,r2,r3,addr) \
    asm volatile("ldmatrix.sync.aligned.m8n8.x4.trans.shared.b16 {%0,%1,%2,%3}, [%4];" \
                 : "=r"(r0), "=r"(r1), "=r"(r2), "=r"(r3) : "r"(addr))
#define MMA16816(d, a0, a1, a2, a3, b0, b1) \
    asm volatile("mma.sync.aligned.m16n8k16.row.col.f32.bf16.bf16.f32 " \
                 "{%0,%1,%2,%3}, {%4,%5,%6,%7}, {%8,%9}, {%0,%1,%2,%3};" \
                 : "+f"((d)[0]), "+f"((d)[1]), "+f"((d)[2]), "+f"((d)[3]) \
                 : "r"(a0), "r"(a1), "r"(a2), "r"(a3), "r"(b0), "r"(b1))

__device__ __forceinline__ uint32_t pack2(float a, float b) {
    __nv_bfloat16 ha = __float2bfloat16_rn(a);
    __nv_bfloat16 hb = __float2bfloat16_rn(b);
    uint16_t ua = *(uint16_t*)&ha, ub = *(uint16_t*)&hb;
    return (uint32_t)ua | ((uint32_t)ub << 16);
}
__device__ __forceinline__ float bf16_val(float v) {
    __nv_bfloat16 h = __float2bfloat16_rn(v);
    return __bfloat162float(h);
}

// ---------------------------------------------------------------------------
__global__ void rope_table_kernel() {
    int idx = blockIdx.x * blockDim.x + threadIdx.x;
    if (idx >= CT * 32) return;
    int t = idx >> 5;
    int i = idx & 31;
    double dinv = pow(10000.0, -(double)(2 * i) / 64.0);
    float invf = (float)dinv;
    float ang = (float)t * invf;
    g_cos[idx] = cosf(ang);
    g_sin[idx] = sinf(ang);
}

// ---------------------------------------------------------------------------
// Split-bf16 HMMA GEMM v2 (R14 verbatim — proven): BK=32, 80KB dyn smem,
// one sync/iter. MODE 0: qkv -> RoPE + scatter; MODE 1: proj -> Out.
// ---------------------------------------------------------------------------
#define LDA 40

template<int MODE>
__global__ __launch_bounds__(512)
void hmma_gemm_kernel(const float* __restrict__ Asrc,
                      const float* __restrict__ Wsrc,
                      float* __restrict__ Out) {
    extern __shared__ __nv_bfloat16 sm_[];
    const uint32_t uS = smem_u32(sm_);
    const int N = (MODE == 0) ? C3 : CC;
    const int tid = threadIdx.x;
    const int wid = tid >> 5, lane = tid & 31;
    const int wm = wid >> 2, wn = wid & 3;
    const int m0 = blockIdx.y * 128, n0 = blockIdx.x * 128;
    const float* __restrict__ Ap = (MODE == 0) ? (Asrc + (size_t)m0 * CC)
                                               : (g_y + (size_t)m0 * CC);

    const int ar = tid >> 2;
    const int as = tid & 3;
    const int wn_ = tid & 127;
    const int wk = tid >> 7;

    float acc[2][4][4];
#pragma unroll
    for (int mi = 0; mi < 2; mi++)
#pragma unroll
        for (int ni = 0; ni < 4; ni++)
#pragma unroll
            for (int r = 0; r < 4; r++) acc[mi][ni][r] = 0.f;

    const int aOff = (wm * 32 + (lane & 15)) * LDA + (lane >> 4) * 8;
    const int bOff = (wn * 32 + ((lane >> 4) & 1) * 8 + (lane & 7)) * LDA
                     + ((lane >> 3) & 1) * 8;

    {
        float4 a0 = *(const float4*)(Ap + (size_t)ar * CC + as * 8);
        float4 a1 = *(const float4*)(Ap + (size_t)ar * CC + as * 8 + 4);
        const float* wp = Wsrc + (size_t)(wk * 8) * N + n0 + wn_;
        float w0 = wp[0], w1 = wp[N], w2 = wp[2*(size_t)N], w3 = wp[3*(size_t)N];
        float w4 = wp[4*(size_t)N], w5 = wp[5*(size_t)N], w6 = wp[6*(size_t)N], w7 = wp[7*(size_t)N];
        int aoff = ar * LDA + as * 8;
        *(uint2*)(sm_ + aoff) = make_uint2(pack2(a0.x, a0.y), pack2(a0.z, a0.w));
        *(uint2*)(sm_ + aoff + 4) = make_uint2(pack2(a1.x, a1.y), pack2(a1.z, a1.w));
        *(uint2*)(sm_ + 10240 + aoff) = make_uint2(
            pack2(a0.x - bf16_val(a0.x), a0.y - bf16_val(a0.y)),
            pack2(a0.z - bf16_val(a0.z), a0.w - bf16_val(a0.w)));
        *(uint2*)(sm_ + 10240 + aoff + 4) = make_uint2(
            pack2(a1.x - bf16_val(a1.x), a1.y - bf16_val(a1.y)),
            pack2(a1.z - bf16_val(a1.z), a1.w - bf16_val(a1.w)));
        int woff = wn_ * LDA + wk * 8;
        *(uint32_t*)(sm_ + 20480 + woff)     = pack2(w0, w1);
        *(uint32_t*)(sm_ + 20480 + woff + 2) = pack2(w2, w3);
        *(uint32_t*)(sm_ + 20480 + woff + 4) = pack2(w4, w5);
        *(uint32_t*)(sm_ + 20480 + woff + 6) = pack2(w6, w7);
        *(uint32_t*)(sm_ + 30720 + woff)     = pack2(w0 - bf16_val(w0), w1 - bf16_val(w1));
        *(uint32_t*)(sm_ + 30720 + woff + 2) = pack2(w2 - bf16_val(w2), w3 - bf16_val(w3));
        *(uint32_t*)(sm_ + 30720 + woff + 4) = pack2(w4 - bf16_val(w4), w5 - bf16_val(w5));
        *(uint32_t*)(sm_ + 30720 + woff + 6) = pack2(w6 - bf16_val(w6), w7 - bf16_val(w7));
    }
    __syncthreads();

    for (int kc = 0; kc < 32; kc++) {
        const int buf = kc & 1;

        float4 a0, a1;
        float w0, w1, w2, w3, w4, w5, w6, w7;
        if (kc + 1 < 32) {
            a0 = *(const float4*)(Ap + (size_t)ar * CC + (kc + 1) * 32 + as * 8);
            a1 = *(const float4*)(Ap + (size_t)ar * CC + (kc + 1) * 32 + as * 8 + 4);
            const float* wp = Wsrc + (size_t)((kc + 1) * 32 + wk * 8) * N + n0 + wn_;
            w0 = wp[0]; w1 = wp[N]; w2 = wp[2*(size_t)N]; w3 = wp[3*(size_t)N];
            w4 = wp[4*(size_t)N]; w5 = wp[5*(size_t)N]; w6 = wp[6*(size_t)N]; w7 = wp[7*(size_t)N];
        }

        const uint32_t bAh = uS + (uint32_t)(buf * 5120) * 2;
        const uint32_t bAl = uS + (uint32_t)(10240 + buf * 5120) * 2;
        const uint32_t bWh = uS + (uint32_t)(20480 + buf * 5120) * 2;
        const uint32_t bWl = uS + (uint32_t)(30720 + buf * 5120) * 2;

#pragma unroll
        for (int ks = 0; ks < 2; ks++) {
            const uint32_t offB0 = (uint32_t)(bOff + ks * 16) * 2;
            const uint32_t offB1 = (uint32_t)(bOff + ks * 16 + 16 * LDA) * 2;
            uint32_t wh0, wh1, wh2, wh3, wh4, wh5, wh6, wh7;
            uint32_t wl0, wl1, wl2, wl3, wl4, wl5, wl6, wl7;
            LDSM4(wh0, wh1, wh2, wh3, bWh + offB0);
            LDSM4(wh4, wh5, wh6, wh7, bWh + offB1);
            LDSM4(wl0, wl1, wl2, wl3, bWl + offB0);
            LDSM4(wl4, wl5, wl6, wl7, bWl + offB1);
#pragma unroll
            for (int mi = 0; mi < 2; mi++) {
                uint32_t offA = (uint32_t)(aOff + ks * 16 + mi * 16 * LDA) * 2;
                uint32_t x0, x1, x2, x3;
                LDSM4(x0, x1, x2, x3, bAh + offA);
                MMA16816(acc[mi][0], x0, x1, x2, x3, wh0, wh1);
                MMA16816(acc[mi][1], x0, x1, x2, x3, wh2, wh3);
                MMA16816(acc[mi][2], x0, x1, x2, x3, wh4, wh5);
                MMA16816(acc[mi][3], x0, x1, x2, x3, wh6, wh7);
                MMA16816(acc[mi][0], x0, x1, x2, x3, wl0, wl1);
                MMA16816(acc[mi][1], x0, x1, x2, x3, wl2, wl3);
                MMA16816(acc[mi][2], x0, x1, x2, x3, wl4, wl5);
                MMA16816(acc[mi][3], x0, x1, x2, x3, wl6, wl7);
                LDSM4(x0, x1, x2, x3, bAl + offA);
                MMA16816(acc[mi][0], x0, x1, x2, x3, wh0, wh1);
                MMA16816(acc[mi][1], x0, x1, x2, x3, wh2, wh3);
                MMA16816(acc[mi][2], x0, x1, x2, x3, wh4, wh5);
                MMA16816(acc[mi][3], x0, x1, x2, x3, wh6, wh7);
            }
        }

        if (kc + 1 < 32) {
            const int b2 = buf ^ 1;
            __nv_bfloat16* Ah_ = sm_ + b2 * 5120;
            __nv_bfloat16* Al_ = sm_ + 10240 + b2 * 5120;
            __nv_bfloat16* Wh_ = sm_ + 20480 + b2 * 5120;
            __nv_bfloat16* Wl_ = sm_ + 30720 + b2 * 5120;
            int aoff = ar * LDA + as * 8;
            *(uint2*)(Ah_ + aoff) = make_uint2(pack2(a0.x, a0.y), pack2(a0.z, a0.w));
            *(uint2*)(Ah_ + aoff + 4) = make_uint2(pack2(a1.x, a1.y), pack2(a1.z, a1.w));
            *(uint2*)(Al_ + aoff) = make_uint2(
                pack2(a0.x - bf16_val(a0.x), a0.y - bf16_val(a0.y)),
                pack2(a0.z - bf16_val(a0.z), a0.w - bf16_val(a0.w)));
            *(uint2*)(Al_ + aoff + 4) = make_uint2(
                pack2(a1.x - bf16_val(a1.x), a1.y - bf16_val(a1.y)),
                pack2(a1.z - bf16_val(a1.z), a1.w - bf16_val(a1.w)));
            int woff = wn_ * LDA + wk * 8;
            *(uint32_t*)(Wh_ + woff)     = pack2(w0, w1);
            *(uint32_t*)(Wh_ + woff + 2) = pack2(w2, w3);
            *(uint32_t*)(Wh_ + woff + 4) = pack2(w4, w5);
            *(uint32_t*)(Wh_ + woff + 6) = pack2(w6, w7);
            *(uint32_t*)(Wl_ + woff)     = pack2(w0 - bf16_val(w0), w1 - bf16_val(w1));
            *(uint32_t*)(Wl_ + woff + 2) = pack2(w2 - bf16_val(w2), w3 - bf16_val(w3));
            *(uint32_t*)(Wl_ + woff + 4) = pack2(w4 - bf16_val(w4), w5 - bf16_val(w5));
            *(uint32_t*)(Wl_ + woff + 6) = pack2(w6 - bf16_val(w6), w7 - bf16_val(w7));
        }
        __syncthreads();
    }

    const int lrow = lane >> 2;
    const int lcol = (lane & 3) * 2;

#pragma unroll
    for (int mi = 0; mi < 2; mi++) {
#pragma unroll
        for (int rh = 0; rh < 2; rh++) {
            const int r = m0 + wm * 32 + mi * 16 + lrow + rh * 8;
            if (MODE == 1) {
                float* dst = Out + (size_t)r * CC + n0 + wn * 32 + lcol;
#pragma unroll
                for (int ni = 0; ni < 4; ni++)
                    *(float2*)(dst + ni * 8) =
                        make_float2(acc[mi][ni][2 * rh], acc[mi][ni][2 * rh + 1]);
            } else {
                const int bI = r >> 11, t = r & 2047;
                const float* ct = g_cos + t * 32;
                const float* st = g_sin + t * 32;
#pragma unroll
                for (int ni = 0; ni < 4; ni++) {
                    const int cg = n0 + wn * 32 + ni * 8 + lcol;
                    const int seg = cg >> 10;
                    const int cs = cg & 1023;
                    const int h = cs >> 6, d = cs & 63;
                    float* base = (seg == 0) ? g_q : ((seg == 1) ? g_k : g_v);
                    float* dst = base + (((size_t)(bI * CH + h) * CT + t) * CD + d);
                    float x1 = acc[mi][ni][2 * rh], x2 = acc[mi][ni][2 * rh + 1];
                    if (seg == 2) {
                        *(float2*)dst = make_float2(x1, x2);
                    } else {
                        float c = ct[d >> 1], s = st[d >> 1];
                        *(float2*)dst = make_float2(x1 * c - x2 * s, x1 * s + x2 * c);
                    }
                }
            }
        }
    }
}

// ---------------------------------------------------------------------------
// HMMA flash attention v2: V kept in natural [kv][d] layout, b-frags via
// ldmatrix.trans (no scalar transpose staging); exp on MUFU (__expf).
// 256 thr = 8 warps x 16 q-rows, BM=128, BN=64. Writes y fp32 to g_y.
// Smem (elems, ALDA=72): Qh 0 | Ql 9216 | Kh 18432 | Kl 23040 | Vh 27648 |
//                        Vl 32256 | total 36864 elems = 73728 B dynamic.
// ---------------------------------------------------------------------------
#define ALDA 72

__global__ __launch_bounds__(256)
void attn_hmma_kernel() {
    extern __shared__ __nv_bfloat16 smA[];
    const uint32_t uS = smem_u32(smA);
    const uint32_t uQh = uS;
    const uint32_t uQl = uS + 9216u * 2;
    const uint32_t uKh = uS + 18432u * 2;
    const uint32_t uKl = uS + 23040u * 2;
    const uint32_t uVh = uS + 27648u * 2;
    const uint32_t uVl = uS + 32256u * 2;

    const int tid = threadIdx.x;
    const int wid = tid >> 5, lane = tid & 31;
    const int bh = blockIdx.y;
    const int qb = gridDim.x - 1 - blockIdx.x;
    const int q0 = qb * 128;
    const float* Qg = g_q + (size_t)bh * CT * CD;
    const float* Kg = g_k + (size_t)bh * CT * CD;
    const float* Vg = g_v + (size_t)bh * CT * CD;

    // ---- load Q (scaled by 0.125) split into Qh/Ql ----
#pragma unroll
    for (int i = 0; i < 8; i++) {
        int idx = tid + 256 * i;
        int row = idx >> 4, seg = idx & 15;
        float4 v = *(const float4*)(Qg + (size_t)(q0 + row) * CD + seg * 4);
        v.x *= 0.125f; v.y *= 0.125f; v.z *= 0.125f; v.w *= 0.125f;
        int off = row * ALDA + seg * 4;
        *(uint2*)(smA + off) = make_uint2(pack2(v.x, v.y), pack2(v.z, v.w));
        *(uint2*)(smA + 9216 + off) = make_uint2(
            pack2(v.x - bf16_val(v.x), v.y - bf16_val(v.y)),
            pack2(v.z - bf16_val(v.z), v.w - bf16_val(v.w)));
    }

    float o[8][4], sacc[8][4];
#pragma unroll
    for (int n = 0; n < 8; n++)
#pragma unroll
        for (int v = 0; v < 4; v++) o[n][v] = 0.f;
    float m0r = -3.0e38f, m1r = -3.0e38f, l0r = 0.f, l1r = 0.f;

    // ldmatrix lane offsets (elems)
    const int aOffQ = (wid * 16 + (lane & 15)) * ALDA + (lane >> 4) * 8;
    const int bOffR = ((lane >> 4) & 1) * 8 + (lane & 7);   // K frag: n-row part
    const int bOffC = ((lane >> 3) & 1) * 8;                // K frag: k-col part
    const int vOffR = ((lane >> 3) & 1) * 8 + (lane & 7);   // V trans: kv-row part
    const int vOffC = (lane >> 4) * 8;                      // V trans: d-col part

    const int ntiles = 2 * qb + 2;
    for (int nt = 0; nt < ntiles; nt++) {
        const int k0 = nt * 64;
        __syncthreads();   // prior tile's frag reads done (and Q written, nt=0)

        // ---- stage K and V tiles (both natural [row][d] layout, split) ----
#pragma unroll
        for (int i = 0; i < 4; i++) {
            int idx = tid + 256 * i;
            int row = idx >> 4, seg = idx & 15;
            int off = row * ALDA + seg * 4;
            float4 kv = *(const float4*)(Kg + (size_t)(k0 + row) * CD + seg * 4);
            *(uint2*)(smA + 18432 + off) = make_uint2(pack2(kv.x, kv.y), pack2(kv.z, kv.w));
            *(uint2*)(smA + 23040 + off) = make_uint2(
                pack2(kv.x - bf16_val(kv.x), kv.y - bf16_val(kv.y)),
                pack2(kv.z - bf16_val(kv.z), kv.w - bf16_val(kv.w)));
            float4 vv = *(const float4*)(Vg + (size_t)(k0 + row) * CD + seg * 4);
            *(uint2*)(smA + 27648 + off) = make_uint2(pack2(vv.x, vv.y), pack2(vv.z, vv.w));
            *(uint2*)(smA + 32256 + off) = make_uint2(
                pack2(vv.x - bf16_val(vv.x), vv.y - bf16_val(vv.y)),
                pack2(vv.z - bf16_val(vv.z), vv.w - bf16_val(vv.w)));
        }
        __syncthreads();

        // ---- S = Qs·K^T (3-way split) ----
#pragma unroll
        for (int n = 0; n < 8; n++)
#pragma unroll
            for (int v = 0; v < 4; v++) sacc[n][v] = 0.f;
#pragma unroll
        for (int ks = 0; ks < 4; ks++) {
            uint32_t offA = (uint32_t)(aOffQ + ks * 16) * 2;
            uint32_t ah0, ah1, ah2, ah3, al0, al1, al2, al3;
            LDSM4(ah0, ah1, ah2, ah3, uQh + offA);
            LDSM4(al0, al1, al2, al3, uQl + offA);
#pragma unroll
            for (int nh = 0; nh < 2; nh++) {
                uint32_t kb = (uint32_t)((nh * 32 + bOffR) * ALDA + ks * 16 + bOffC) * 2;
                uint32_t b0, b1, b2, b3, b4, b5, b6, b7;
                LDSM4(b0, b1, b2, b3, uKh + kb);
                LDSM4(b4, b5, b6, b7, uKh + kb + 16 * ALDA * 2);
                MMA16816(sacc[nh * 4 + 0], ah0, ah1, ah2, ah3, b0, b1);
                MMA16816(sacc[nh * 4 + 1], ah0, ah1, ah2, ah3, b2, b3);
                MMA16816(sacc[nh * 4 + 2], ah0, ah1, ah2, ah3, b4, b5);
                MMA16816(sacc[nh * 4 + 3], ah0, ah1, ah2, ah3, b6, b7);
                MMA16816(sacc[nh * 4 + 0], al0, al1, al2, al3, b0, b1);
                MMA16816(sacc[nh * 4 + 1], al0, al1, al2, al3, b2, b3);
                MMA16816(sacc[nh * 4 + 2], al0, al1, al2, al3, b4, b5);
                MMA16816(sacc[nh * 4 + 3], al0, al1, al2, al3, b6, b7);
                LDSM4(b0, b1, b2, b3, uKl + kb);
                LDSM4(b4, b5, b6, b7, uKl + kb + 16 * ALDA * 2);
                MMA16816(sacc[nh * 4 + 0], ah0, ah1, ah2, ah3, b0, b1);
                MMA16816(sacc[nh * 4 + 1], ah0, ah1, ah2, ah3, b2, b3);
                MMA16816(sacc[nh * 4 + 2], ah0, ah1, ah2, ah3, b4, b5);
                MMA16816(sacc[nh * 4 + 3], ah0, ah1, ah2, ah3, b6, b7);
            }
        }

        // ---- causal mask (diagonal tiles only) ----
        if (nt >= 2 * qb) {
            const int r0 = q0 + wid * 16 + (lane >> 2);
#pragma unroll
            for (int n = 0; n < 8; n++) {
                int colb = k0 + ((n >> 2) << 5) + ((n & 3) << 3) + (lane & 3) * 2;
#pragma unroll
                for (int v = 0; v < 4; v++) {
                    int col = colb + (v & 1);
                    int row = r0 + (v >> 1) * 8;
                    if (col > row) sacc[n][v] = -1.0e30f;
                }
            }
        }

        // ---- online softmax (exp on MUFU) ----
        float rx0 = -3.0e38f, rx1 = -3.0e38f;
#pragma unroll
        for (int n = 0; n < 8; n++) {
            rx0 = fmaxf(rx0, fmaxf(sacc[n][0], sacc[n][1]));
            rx1 = fmaxf(rx1, fmaxf(sacc[n][2], sacc[n][3]));
        }
        rx0 = fmaxf(rx0, __shfl_xor_sync(0xffffffffu, rx0, 1));
        rx0 = fmaxf(rx0, __shfl_xor_sync(0xffffffffu, rx0, 2));
        rx1 = fmaxf(rx1, __shfl_xor_sync(0xffffffffu, rx1, 1));
        rx1 = fmaxf(rx1, __shfl_xor_sync(0xffffffffu, rx1, 2));
        float mn0 = fmaxf(m0r, rx0), mn1 = fmaxf(m1r, rx1);
        float sf0 = __expf(m0r - mn0), sf1 = __expf(m1r - mn1);
        m0r = mn0; m1r = mn1;
        float rs0 = 0.f, rs1 = 0.f;
#pragma unroll
        for (int n = 0; n < 8; n++) {
            float p0 = __expf(sacc[n][0] - mn0);
            float p1 = __expf(sacc[n][1] - mn0);
            float p2 = __expf(sacc[n][2] - mn1);
            float p3 = __expf(sacc[n][3] - mn1);
            sacc[n][0] = p0; sacc[n][1] = p1; sacc[n][2] = p2; sacc[n][3] = p3;
            rs0 += p0 + p1; rs1 += p2 + p3;
            o[n][0] *= sf0; o[n][1] *= sf0; o[n][2] *= sf1; o[n][3] *= sf1;
        }
        rs0 += __shfl_xor_sync(0xffffffffu, rs0, 1);
        rs0 += __shfl_xor_sync(0xffffffffu, rs0, 2);
        rs1 += __shfl_xor_sync(0xffffffffu, rs1, 1);
        rs1 += __shfl_xor_sync(0xffffffffu, rs1, 2);
        l0r = l0r * sf0 + rs0;
        l1r = l1r * sf1 + rs1;

        // ---- O += P·V (P a-frags from sacc; V b-frags via ldmatrix.trans) ----
#pragma unroll
        for (int ks = 0; ks < 4; ks++) {
            float p00 = sacc[2 * ks][0],     p01 = sacc[2 * ks][1];
            float p02 = sacc[2 * ks][2],     p03 = sacc[2 * ks][3];
            float p10 = sacc[2 * ks + 1][0], p11 = sacc[2 * ks + 1][1];
            float p12 = sacc[2 * ks + 1][2], p13 = sacc[2 * ks + 1][3];
            uint32_t ah0 = pack2(p00, p01), ah1 = pack2(p02, p03);
            uint32_t ah2 = pack2(p10, p11), ah3 = pack2(p12, p13);
            uint32_t al0 = pack2(p00 - bf16_val(p00), p01 - bf16_val(p01));
            uint32_t al1 = pack2(p02 - bf16_val(p02), p03 - bf16_val(p03));
            uint32_t al2 = pack2(p10 - bf16_val(p10), p11 - bf16_val(p11));
            uint32_t al3 = pack2(p12 - bf16_val(p12), p13 - bf16_val(p13));
            // V frag base: rows kv = ks*16 + vOffR, cols d = nh*32 + vOffC (+16)
#pragma unroll
            for (int nh = 0; nh < 2; nh++) {
                uint32_t vb = (uint32_t)((ks * 16 + vOffR) * ALDA + nh * 32 + vOffC) * 2;
                uint32_t b0, b1, b2, b3, b4, b5, b6, b7;
                LDSM4T(b0, b1, b2, b3, uVh + vb);
                LDSM4T(b4, b5, b6, b7, uVh + vb + 16 * 2);
                MMA16816(o[nh * 4 + 0], ah0, ah1, ah2, ah3, b0, b1);
                MMA16816(o[nh * 4 + 1], ah0, ah1, ah2, ah3, b2, b3);
                MMA16816(o[nh * 4 + 2], ah0, ah1, ah2, ah3, b4, b5);
                MMA16816(o[nh * 4 + 3], ah0, ah1, ah2, ah3, b6, b7);
                MMA16816(o[nh * 4 + 0], al0, al1, al2, al3, b0, b1);
                MMA16816(o[nh * 4 + 1], al0, al1, al2, al3, b2, b3);
                MMA16816(o[nh * 4 + 2], al0, al1, al2, al3, b4, b5);
                MMA16816(o[nh * 4 + 3], al0, al1, al2, al3, b6, b7);
                LDSM4T(b0, b1, b2, b3, uVl + vb);
                LDSM4T(b4, b5, b6, b7, uVl + vb + 16 * 2);
                MMA16816(o[nh * 4 + 0], ah0, ah1, ah2, ah3, b0, b1);
                MMA16816(o[nh * 4 + 1], ah0, ah1, ah2, ah3, b2, b3);
                MMA16816(o[nh * 4 + 2], ah0, ah1, ah2, ah3, b4, b5);
                MMA16816(o[nh * 4 + 3], ah0, ah1, ah2, ah3, b6, b7);
            }
        }
    }

    // ---- write y = O / l to g_y [B,T,C] ----
    const int bI = bh >> 4, h = bh & 15;
    const float inv0 = 1.f / l0r, inv1 = 1.f / l1r;
    const int row0 = q0 + wid * 16 + (lane >> 2);
#pragma unroll
    for (int rh = 0; rh < 2; rh++) {
        int row = row0 + rh * 8;
        float invl = rh ? inv1 : inv0;
        float* dst = g_y + ((size_t)(bI * CT + row)) * CC + h * CD + (lane & 3) * 2;
#pragma unroll
        for (int n = 0; n < 8; n++) {
            int d = ((n >> 2) << 5) + ((n & 3) << 3);
            *(float2*)(dst + d) = make_float2(o[n][2 * rh] * invl, o[n][2 * rh + 1] * invl);
        }
    }
}

// ---------------------------------------------------------------------------
extern "C" void kernel_launch(void* const* d_in, const int* in_sizes, int n_in,
                              void* d_out, int out_size) {
    const float* x      = (const float*)d_in[0];
    const float* W_attn = (const float*)d_in[1];
    const float* W_proj = (const float*)d_in[2];
    float* out = (float*)d_out;
    (void)in_sizes; (void)n_in; (void)out_size;

    static bool attrs_set = false;
    if (!attrs_set) {
        cudaFuncSetAttribute(attn_hmma_kernel,
                             cudaFuncAttributeMaxDynamicSharedMemorySize, 73728);
        cudaFuncSetAttribute(hmma_gemm_kernel<0>,
                             cudaFuncAttributeMaxDynamicSharedMemorySize, 81920);
        cudaFuncSetAttribute(hmma_gemm_kernel<1>,
                             cudaFuncAttributeMaxDynamicSharedMemorySize, 81920);
        attrs_set = true;
    }

    rope_table_kernel<<<(CT * 32 + 255) / 256, 256>>>();

    {
        dim3 g1(C3 / 128, CM / 128);
        hmma_gemm_kernel<0><<<g1, 512, 81920>>>(x, W_attn, nullptr);
    }
    {
        dim3 g2(CT / 128, CB * CH);
        attn_hmma_kernel<<<g2, 256, 73728>>>();
    }
    {
        dim3 g3(CC / 128, CM / 128);
        hmma_gemm_kernel<1><<<g3, 512, 81920>>>(nullptr, W_proj, out);
    }
}

// round 16
// speedup vs baseline: 2.6270x; 1.1815x over previous
#include <cuda_runtime.h>
#include <cuda_bf16.h>
#include <math.h>
#include <stdint.h>

// Shapes (fixed)
#define CB 4
#define CT 2048
#define CC 1024
#define CH 16
#define CD 64
#define CM (CB*CT)     // 8192
#define C3 (3*CC)      // 3072

// ---------------- device scratch: EXACT R1 set (proven to pass) ------------
__device__ float g_q[(size_t)CB*CH*CT*CD];
__device__ float g_k[(size_t)CB*CH*CT*CD];
__device__ float g_v[(size_t)CB*CH*CT*CD];
__device__ float g_y[(size_t)CM*CC];
__device__ float g_cos[CT*32];
__device__ float g_sin[CT*32];

// ---------------- PTX helpers (compute_100-safe only) -----------------------
__device__ __forceinline__ uint32_t smem_u32(const void* p) {
    uint32_t a;
    asm("{ .reg .u64 t; cvta.to.shared.u64 t, %1; cvt.u32.u64 %0, t; }" : "=r"(a) : "l"(p));
    return a;
}
#define LDSM4(r0,r1,r2,r3,addr) \
    asm volatile("ldmatrix.sync.aligned.m8n8.x4.shared.b16 {%0,%1,%2,%3}, [%4];" \
                 : "=r"(r0), "=r"(r1), "=r"(r2), "=r"(r3) : "r"(addr))
#define LDSM4T(r0,r1,r2,r3,addr) \
    asm volatile("ldmatrix.sync.aligned.m8n8.x4.trans.shared.b16 {%0,%1,%2,%3}, [%4];" \
                 : "=r"(r0), "=r"(r1), "=r"(r2), "=r"(r3) : "r"(addr))
#define MMA16816(d, a0, a1, a2, a3, b0, b1) \
    asm volatile("mma.sync.aligned.m16n8k16.row.col.f32.bf16.bf16.f32 " \
                 "{%0,%1,%2,%3}, {%4,%5,%6,%7}, {%8,%9}, {%0,%1,%2,%3};" \
                 : "+f"((d)[0]), "+f"((d)[1]), "+f"((d)[2]), "+f"((d)[3]) \
                 : "r"(a0), "r"(a1), "r"(a2), "r"(a3), "r"(b0), "r"(b1))

__device__ __forceinline__ uint32_t pack2(float a, float b) {
    __nv_bfloat16 ha = __float2bfloat16_rn(a);
    __nv_bfloat16 hb = __float2bfloat16_rn(b);
    uint16_t ua = *(uint16_t*)&ha, ub = *(uint16_t*)&hb;
    return (uint32_t)ua | ((uint32_t)ub << 16);
}
__device__ __forceinline__ float bf16_val(float v) {
    __nv_bfloat16 h = __float2bfloat16_rn(v);
    return __bfloat162float(h);
}

// ---------------------------------------------------------------------------
__global__ void rope_table_kernel() {
    int idx = blockIdx.x * blockDim.x + threadIdx.x;
    if (idx >= CT * 32) return;
    int t = idx >> 5;
    int i = idx & 31;
    double dinv = pow(10000.0, -(double)(2 * i) / 64.0);
    float invf = (float)dinv;
    float ang = (float)t * invf;
    g_cos[idx] = cosf(ang);
    g_sin[idx] = sinf(ang);
}

// ---------------------------------------------------------------------------
// Split-bf16 HMMA GEMM v3: 2 CTAs/SM via __launch_bounds__(512,2) (64-reg cap).
// Low-pressure loop: staging (LDG+cvt+STS) in the tail AFTER the MMA section;
// inner passes keep only one W fragment set live at a time.
// C = Ah.Wh^T + Ah.Wl^T + Al.Wh^T over K=1024 (32 chunks of 32).
// 128x128 block, 512 threads = 16 warps (4x4), warp tile 32x32 (acc=32).
// Smem elem offsets (LDA=40): Ah buf*5120 | Al 10240+ | Wh 20480+ | Wl 30720+
// MODE 0: qkv (A=x) -> RoPE + scatter;  MODE 1: proj (A=g_y) -> Out.
// ---------------------------------------------------------------------------
#define LDA 40

#define GEMM_STAGE(kc_, b_) do {                                                \
    float4 a0_ = *(const float4*)(Ap + (size_t)ar * CC + (kc_) * 32 + as * 8);  \
    float4 a1_ = *(const float4*)(Ap + (size_t)ar * CC + (kc_) * 32 + as * 8 + 4); \
    const float* wp_ = Wsrc + (size_t)((kc_) * 32 + wk * 8) * N + n0 + wn_;     \
    float w0_ = wp_[0], w1_ = wp_[N], w2_ = wp_[2*(size_t)N], w3_ = wp_[3*(size_t)N]; \
    float w4_ = wp_[4*(size_t)N], w5_ = wp_[5*(size_t)N], w6_ = wp_[6*(size_t)N], w7_ = wp_[7*(size_t)N]; \
    __nv_bfloat16* Ah_ = sm_ + (b_) * 5120;                                     \
    __nv_bfloat16* Al_ = sm_ + 10240 + (b_) * 5120;                             \
    __nv_bfloat16* Wh_ = sm_ + 20480 + (b_) * 5120;                             \
    __nv_bfloat16* Wl_ = sm_ + 30720 + (b_) * 5120;                             \
    int aoff_ = ar * LDA + as * 8;                                              \
    *(uint2*)(Ah_ + aoff_)     = make_uint2(pack2(a0_.x, a0_.y), pack2(a0_.z, a0_.w)); \
    *(uint2*)(Ah_ + aoff_ + 4) = make_uint2(pack2(a1_.x, a1_.y), pack2(a1_.z, a1_.w)); \
    *(uint2*)(Al_ + aoff_)     = make_uint2(                                    \
        pack2(a0_.x - bf16_val(a0_.x), a0_.y - bf16_val(a0_.y)),                \
        pack2(a0_.z - bf16_val(a0_.z), a0_.w - bf16_val(a0_.w)));               \
    *(uint2*)(Al_ + aoff_ + 4) = make_uint2(                                    \
        pack2(a1_.x - bf16_val(a1_.x), a1_.y - bf16_val(a1_.y)),                \
        pack2(a1_.z - bf16_val(a1_.z), a1_.w - bf16_val(a1_.w)));               \
    int woff_ = wn_ * LDA + wk * 8;                                             \
    *(uint32_t*)(Wh_ + woff_)     = pack2(w0_, w1_);                            \
    *(uint32_t*)(Wh_ + woff_ + 2) = pack2(w2_, w3_);                            \
    *(uint32_t*)(Wh_ + woff_ + 4) = pack2(w4_, w5_);                            \
    *(uint32_t*)(Wh_ + woff_ + 6) = pack2(w6_, w7_);                            \
    *(uint32_t*)(Wl_ + woff_)     = pack2(w0_ - bf16_val(w0_), w1_ - bf16_val(w1_)); \
    *(uint32_t*)(Wl_ + woff_ + 2) = pack2(w2_ - bf16_val(w2_), w3_ - bf16_val(w3_)); \
    *(uint32_t*)(Wl_ + woff_ + 4) = pack2(w4_ - bf16_val(w4_), w5_ - bf16_val(w5_)); \
    *(uint32_t*)(Wl_ + woff_ + 6) = pack2(w6_ - bf16_val(w6_), w7_ - bf16_val(w7_)); \
} while (0)

template<int MODE>
__global__ __launch_bounds__(512, 2)
void hmma_gemm_kernel(const float* __restrict__ Asrc,
                      const float* __restrict__ Wsrc,
                      float* __restrict__ Out) {
    extern __shared__ __nv_bfloat16 sm_[];
    const uint32_t uS = smem_u32(sm_);
    const int N = (MODE == 0) ? C3 : CC;
    const int tid = threadIdx.x;
    const int wid = tid >> 5, lane = tid & 31;
    const int wm = wid >> 2, wn = wid & 3;
    const int m0 = blockIdx.y * 128, n0 = blockIdx.x * 128;
    const float* __restrict__ Ap = (MODE == 0) ? (Asrc + (size_t)m0 * CC)
                                               : (g_y + (size_t)m0 * CC);

    const int ar = tid >> 2;
    const int as = tid & 3;
    const int wn_ = tid & 127;
    const int wk = tid >> 7;

    float acc[2][4][4];
#pragma unroll
    for (int mi = 0; mi < 2; mi++)
#pragma unroll
        for (int ni = 0; ni < 4; ni++)
#pragma unroll
            for (int r = 0; r < 4; r++) acc[mi][ni][r] = 0.f;

    const int aOff = (wm * 32 + (lane & 15)) * LDA + (lane >> 4) * 8;
    const int bOff = (wn * 32 + ((lane >> 4) & 1) * 8 + (lane & 7)) * LDA
                     + ((lane >> 3) & 1) * 8;

    GEMM_STAGE(0, 0);
    __syncthreads();

    for (int kc = 0; kc < 32; kc++) {
        const int buf = kc & 1;
        const uint32_t bAh = uS + (uint32_t)(buf * 5120) * 2;
        const uint32_t bAl = uS + (uint32_t)(10240 + buf * 5120) * 2;
        const uint32_t bWh = uS + (uint32_t)(20480 + buf * 5120) * 2;
        const uint32_t bWl = uS + (uint32_t)(30720 + buf * 5120) * 2;

#pragma unroll
        for (int ks = 0; ks < 2; ks++) {
            const uint32_t offB0 = (uint32_t)(bOff + ks * 16) * 2;
            const uint32_t offB1 = (uint32_t)(bOff + ks * 16 + 16 * LDA) * 2;
            uint32_t w0, w1, w2, w3, w4, w5, w6, w7;
            // pass 1+2: (Ah + Al) x Wh  — only wh live
            LDSM4(w0, w1, w2, w3, bWh + offB0);
            LDSM4(w4, w5, w6, w7, bWh + offB1);
#pragma unroll
            for (int mi = 0; mi < 2; mi++) {
                uint32_t offA = (uint32_t)(aOff + ks * 16 + mi * 16 * LDA) * 2;
                uint32_t x0, x1, x2, x3;
                LDSM4(x0, x1, x2, x3, bAh + offA);
                MMA16816(acc[mi][0], x0, x1, x2, x3, w0, w1);
                MMA16816(acc[mi][1], x0, x1, x2, x3, w2, w3);
                MMA16816(acc[mi][2], x0, x1, x2, x3, w4, w5);
                MMA16816(acc[mi][3], x0, x1, x2, x3, w6, w7);
                LDSM4(x0, x1, x2, x3, bAl + offA);
                MMA16816(acc[mi][0], x0, x1, x2, x3, w0, w1);
                MMA16816(acc[mi][1], x0, x1, x2, x3, w2, w3);
                MMA16816(acc[mi][2], x0, x1, x2, x3, w4, w5);
                MMA16816(acc[mi][3], x0, x1, x2, x3, w6, w7);
            }
            // pass 3: Ah x Wl — wl reuses the same registers
            LDSM4(w0, w1, w2, w3, bWl + offB0);
            LDSM4(w4, w5, w6, w7, bWl + offB1);
#pragma unroll
            for (int mi = 0; mi < 2; mi++) {
                uint32_t offA = (uint32_t)(aOff + ks * 16 + mi * 16 * LDA) * 2;
                uint32_t x0, x1, x2, x3;
                LDSM4(x0, x1, x2, x3, bAh + offA);
                MMA16816(acc[mi][0], x0, x1, x2, x3, w0, w1);
                MMA16816(acc[mi][1], x0, x1, x2, x3, w2, w3);
                MMA16816(acc[mi][2], x0, x1, x2, x3, w4, w5);
                MMA16816(acc[mi][3], x0, x1, x2, x3, w6, w7);
            }
        }

        // ---- tail: stage next chunk into buf^1 (LDG latency covered by co-CTA)
        if (kc + 1 < 32) {
            GEMM_STAGE(kc + 1, buf ^ 1);
        }
        __syncthreads();   // publishes buf^1; protects buf until next overwrite
    }

    // ------------- epilogue --------------------------------------------------
    const int lrow = lane >> 2;
    const int lcol = (lane & 3) * 2;

#pragma unroll
    for (int mi = 0; mi < 2; mi++) {
#pragma unroll
        for (int rh = 0; rh < 2; rh++) {
            const int r = m0 + wm * 32 + mi * 16 + lrow + rh * 8;
            if (MODE == 1) {
                float* dst = Out + (size_t)r * CC + n0 + wn * 32 + lcol;
#pragma unroll
                for (int ni = 0; ni < 4; ni++)
                    *(float2*)(dst + ni * 8) =
                        make_float2(acc[mi][ni][2 * rh], acc[mi][ni][2 * rh + 1]);
            } else {
                const int bI = r >> 11, t = r & 2047;
                const float* ct = g_cos + t * 32;
                const float* st = g_sin + t * 32;
#pragma unroll
                for (int ni = 0; ni < 4; ni++) {
                    const int cg = n0 + wn * 32 + ni * 8 + lcol;
                    const int seg = cg >> 10;
                    const int cs = cg & 1023;
                    const int h = cs >> 6, d = cs & 63;
                    float* base = (seg == 0) ? g_q : ((seg == 1) ? g_k : g_v);
                    float* dst = base + (((size_t)(bI * CH + h) * CT + t) * CD + d);
                    float x1 = acc[mi][ni][2 * rh], x2 = acc[mi][ni][2 * rh + 1];
                    if (seg == 2) {
                        *(float2*)dst = make_float2(x1, x2);
                    } else {
                        float c = ct[d >> 1], s = st[d >> 1];
                        *(float2*)dst = make_float2(x1 * c - x2 * s, x1 * s + x2 * c);
                    }
                }
            }
        }
    }
}

// ---------------------------------------------------------------------------
// HMMA flash attention v2 (R15 verbatim — proven): V natural layout +
// ldmatrix.trans, exp on MUFU. Writes y fp32 to g_y.
// ---------------------------------------------------------------------------
#define ALDA 72

__global__ __launch_bounds__(256)
void attn_hmma_kernel() {
    extern __shared__ __nv_bfloat16 smA[];
    const uint32_t uS = smem_u32(smA);
    const uint32_t uQh = uS;
    const uint32_t uQl = uS + 9216u * 2;
    const uint32_t uKh = uS + 18432u * 2;
    const uint32_t uKl = uS + 23040u * 2;
    const uint32_t uVh = uS + 27648u * 2;
    const uint32_t uVl = uS + 32256u * 2;

    const int tid = threadIdx.x;
    const int wid = tid >> 5, lane = tid & 31;
    const int bh = blockIdx.y;
    const int qb = gridDim.x - 1 - blockIdx.x;
    const int q0 = qb * 128;
    const float* Qg = g_q + (size_t)bh * CT * CD;
    const float* Kg = g_k + (size_t)bh * CT * CD;
    const float* Vg = g_v + (size_t)bh * CT * CD;

#pragma unroll
    for (int i = 0; i < 8; i++) {
        int idx = tid + 256 * i;
        int row = idx >> 4, seg = idx & 15;
        float4 v = *(const float4*)(Qg + (size_t)(q0 + row) * CD + seg * 4);
        v.x *= 0.125f; v.y *= 0.125f; v.z *= 0.125f; v.w *= 0.125f;
        int off = row * ALDA + seg * 4;
        *(uint2*)(smA + off) = make_uint2(pack2(v.x, v.y), pack2(v.z, v.w));
        *(uint2*)(smA + 9216 + off) = make_uint2(
            pack2(v.x - bf16_val(v.x), v.y - bf16_val(v.y)),
            pack2(v.z - bf16_val(v.z), v.w - bf16_val(v.w)));
    }

    float o[8][4], sacc[8][4];
#pragma unroll
    for (int n = 0; n < 8; n++)
#pragma unroll
        for (int v = 0; v < 4; v++) o[n][v] = 0.f;
    float m0r = -3.0e38f, m1r = -3.0e38f, l0r = 0.f, l1r = 0.f;

    const int aOffQ = (wid * 16 + (lane & 15)) * ALDA + (lane >> 4) * 8;
    const int bOffR = ((lane >> 4) & 1) * 8 + (lane & 7);
    const int bOffC = ((lane >> 3) & 1) * 8;
    const int vOffR = ((lane >> 3) & 1) * 8 + (lane & 7);
    const int vOffC = (lane >> 4) * 8;

    const int ntiles = 2 * qb + 2;
    for (int nt = 0; nt < ntiles; nt++) {
        const int k0 = nt * 64;
        __syncthreads();

#pragma unroll
        for (int i = 0; i < 4; i++) {
            int idx = tid + 256 * i;
            int row = idx >> 4, seg = idx & 15;
            int off = row * ALDA + seg * 4;
            float4 kv = *(const float4*)(Kg + (size_t)(k0 + row) * CD + seg * 4);
            *(uint2*)(smA + 18432 + off) = make_uint2(pack2(kv.x, kv.y), pack2(kv.z, kv.w));
            *(uint2*)(smA + 23040 + off) = make_uint2(
                pack2(kv.x - bf16_val(kv.x), kv.y - bf16_val(kv.y)),
                pack2(kv.z - bf16_val(kv.z), kv.w - bf16_val(kv.w)));
            float4 vv = *(const float4*)(Vg + (size_t)(k0 + row) * CD + seg * 4);
            *(uint2*)(smA + 27648 + off) = make_uint2(pack2(vv.x, vv.y), pack2(vv.z, vv.w));
            *(uint2*)(smA + 32256 + off) = make_uint2(
                pack2(vv.x - bf16_val(vv.x), vv.y - bf16_val(vv.y)),
                pack2(vv.z - bf16_val(vv.z), vv.w - bf16_val(vv.w)));
        }
        __syncthreads();

#pragma unroll
        for (int n = 0; n < 8; n++)
#pragma unroll
            for (int v = 0; v < 4; v++) sacc[n][v] = 0.f;
#pragma unroll
        for (int ks = 0; ks < 4; ks++) {
            uint32_t offA = (uint32_t)(aOffQ + ks * 16) * 2;
            uint32_t ah0, ah1, ah2, ah3, al0, al1, al2, al3;
            LDSM4(ah0, ah1, ah2, ah3, uQh + offA);
            LDSM4(al0, al1, al2, al3, uQl + offA);
#pragma unroll
            for (int nh = 0; nh < 2; nh++) {
                uint32_t kb = (uint32_t)((nh * 32 + bOffR) * ALDA + ks * 16 + bOffC) * 2;
                uint32_t b0, b1, b2, b3, b4, b5, b6, b7;
                LDSM4(b0, b1, b2, b3, uKh + kb);
                LDSM4(b4, b5, b6, b7, uKh + kb + 16 * ALDA * 2);
                MMA16816(sacc[nh * 4 + 0], ah0, ah1, ah2, ah3, b0, b1);
                MMA16816(sacc[nh * 4 + 1], ah0, ah1, ah2, ah3, b2, b3);
                MMA16816(sacc[nh * 4 + 2], ah0, ah1, ah2, ah3, b4, b5);
                MMA16816(sacc[nh * 4 + 3], ah0, ah1, ah2, ah3, b6, b7);
                MMA16816(sacc[nh * 4 + 0], al0, al1, al2, al3, b0, b1);
                MMA16816(sacc[nh * 4 + 1], al0, al1, al2, al3, b2, b3);
                MMA16816(sacc[nh * 4 + 2], al0, al1, al2, al3, b4, b5);
                MMA16816(sacc[nh * 4 + 3], al0, al1, al2, al3, b6, b7);
                LDSM4(b0, b1, b2, b3, uKl + kb);
                LDSM4(b4, b5, b6, b7, uKl + kb + 16 * ALDA * 2);
                MMA16816(sacc[nh * 4 + 0], ah0, ah1, ah2, ah3, b0, b1);
                MMA16816(sacc[nh * 4 + 1], ah0, ah1, ah2, ah3, b2, b3);
                MMA16816(sacc[nh * 4 + 2], ah0, ah1, ah2, ah3, b4, b5);
                MMA16816(sacc[nh * 4 + 3], ah0, ah1, ah2, ah3, b6, b7);
            }
        }

        if (nt >= 2 * qb) {
            const int r0 = q0 + wid * 16 + (lane >> 2);
#pragma unroll
            for (int n = 0; n < 8; n++) {
                int colb = k0 + ((n >> 2) << 5) + ((n & 3) << 3) + (lane & 3) * 2;
#pragma unroll
                for (int v = 0; v < 4; v++) {
                    int col = colb + (v & 1);
                    int row = r0 + (v >> 1) * 8;
                    if (col > row) sacc[n][v] = -1.0e30f;
                }
            }
        }

        float rx0 = -3.0e38f, rx1 = -3.0e38f;
#pragma unroll
        for (int n = 0; n < 8; n++) {
            rx0 = fmaxf(rx0, fmaxf(sacc[n][0], sacc[n][1]));
            rx1 = fmaxf(rx1, fmaxf(sacc[n][2], sacc[n][3]));
        }
        rx0 = fmaxf(rx0, __shfl_xor_sync(0xffffffffu, rx0, 1));
        rx0 = fmaxf(rx0, __shfl_xor_sync(0xffffffffu, rx0, 2));
        rx1 = fmaxf(rx1, __shfl_xor_sync(0xffffffffu, rx1, 1));
        rx1 = fmaxf(rx1, __shfl_xor_sync(0xffffffffu, rx1, 2));
        float mn0 = fmaxf(m0r, rx0), mn1 = fmaxf(m1r, rx1);
        float sf0 = __expf(m0r - mn0), sf1 = __expf(m1r - mn1);
        m0r = mn0; m1r = mn1;
        float rs0 = 0.f, rs1 = 0.f;
#pragma unroll
        for (int n = 0; n < 8; n++) {
            float p0 = __expf(sacc[n][0] - mn0);
            float p1 = __expf(sacc[n][1] - mn0);
            float p2 = __expf(sacc[n][2] - mn1);
            float p3 = __expf(sacc[n][3] - mn1);
            sacc[n][0] = p0; sacc[n][1] = p1; sacc[n][2] = p2; sacc[n][3] = p3;
            rs0 += p0 + p1; rs1 += p2 + p3;
            o[n][0] *= sf0; o[n][1] *= sf0; o[n][2] *= sf1; o[n][3] *= sf1;
        }
        rs0 += __shfl_xor_sync(0xffffffffu, rs0, 1);
        rs0 += __shfl_xor_sync(0xffffffffu, rs0, 2);
        rs1 += __shfl_xor_sync(0xffffffffu, rs1, 1);
        rs1 += __shfl_xor_sync(0xffffffffu, rs1, 2);
        l0r = l0r * sf0 + rs0;
        l1r = l1r * sf1 + rs1;

#pragma unroll
        for (int ks = 0; ks < 4; ks++) {
            float p00 = sacc[2 * ks][0],     p01 = sacc[2 * ks][1];
            float p02 = sacc[2 * ks][2],     p03 = sacc[2 * ks][3];
            float p10 = sacc[2 * ks + 1][0], p11 = sacc[2 * ks + 1][1];
            float p12 = sacc[2 * ks + 1][2], p13 = sacc[2 * ks + 1][3];
            uint32_t ah0 = pack2(p00, p01), ah1 = pack2(p02, p03);
            uint32_t ah2 = pack2(p10, p11), ah3 = pack2(p12, p13);
            uint32_t al0 = pack2(p00 - bf16_val(p00), p01 - bf16_val(p01));
            uint32_t al1 = pack2(p02 - bf16_val(p02), p03 - bf16_val(p03));
            uint32_t al2 = pack2(p10 - bf16_val(p10), p11 - bf16_val(p11));
            uint32_t al3 = pack2(p12 - bf16_val(p12), p13 - bf16_val(p13));
#pragma unroll
            for (int nh = 0; nh < 2; nh++) {
                uint32_t vb = (uint32_t)((ks * 16 + vOffR) * ALDA + nh * 32 + vOffC) * 2;
                uint32_t b0, b1, b2, b3, b4, b5, b6, b7;
                LDSM4T(b0, b1, b2, b3, uVh + vb);
                LDSM4T(b4, b5, b6, b7, uVh + vb + 16 * 2);
                MMA16816(o[nh * 4 + 0], ah0, ah1, ah2, ah3, b0, b1);
                MMA16816(o[nh * 4 + 1], ah0, ah1, ah2, ah3, b2, b3);
                MMA16816(o[nh * 4 + 2], ah0, ah1, ah2, ah3, b4, b5);
                MMA16816(o[nh * 4 + 3], ah0, ah1, ah2, ah3, b6, b7);
                MMA16816(o[nh * 4 + 0], al0, al1, al2, al3, b0, b1);
                MMA16816(o[nh * 4 + 1], al0, al1, al2, al3, b2, b3);
                MMA16816(o[nh * 4 + 2], al0, al1, al2, al3, b4, b5);
                MMA16816(o[nh * 4 + 3], al0, al1, al2, al3, b6, b7);
                LDSM4T(b0, b1, b2, b3, uVl + vb);
                LDSM4T(b4, b5, b6, b7, uVl + vb + 16 * 2);
                MMA16816(o[nh * 4 + 0], ah0, ah1, ah2, ah3, b0, b1);
                MMA16816(o[nh * 4 + 1], ah0, ah1, ah2, ah3, b2, b3);
                MMA16816(o[nh * 4 + 2], ah0, ah1, ah2, ah3, b4, b5);
                MMA16816(o[nh * 4 + 3], ah0, ah1, ah2, ah3, b6, b7);
            }
        }
    }

    const int bI = bh >> 4, h = bh & 15;
    const float inv0 = 1.f / l0r, inv1 = 1.f / l1r;
    const int row0 = q0 + wid * 16 + (lane >> 2);
#pragma unroll
    for (int rh = 0; rh < 2; rh++) {
        int row = row0 + rh * 8;
        float invl = rh ? inv1 : inv0;
        float* dst = g_y + ((size_t)(bI * CT + row)) * CC + h * CD + (lane & 3) * 2;
#pragma unroll
        for (int n = 0; n < 8; n++) {
            int d = ((n >> 2) << 5) + ((n & 3) << 3);
            *(float2*)(dst + d) = make_float2(o[n][2 * rh] * invl, o[n][2 * rh + 1] * invl);
        }
    }
}

// ---------------------------------------------------------------------------
extern "C" void kernel_launch(void* const* d_in, const int* in_sizes, int n_in,
                              void* d_out, int out_size) {
    const float* x      = (const float*)d_in[0];
    const float* W_attn = (const float*)d_in[1];
    const float* W_proj = (const float*)d_in[2];
    float* out = (float*)d_out;
    (void)in_sizes; (void)n_in; (void)out_size;

    static bool attrs_set = false;
    if (!attrs_set) {
        cudaFuncSetAttribute(attn_hmma_kernel,
                             cudaFuncAttributeMaxDynamicSharedMemorySize, 73728);
        cudaFuncSetAttribute(hmma_gemm_kernel<0>,
                             cudaFuncAttributeMaxDynamicSharedMemorySize, 81920);
        cudaFuncSetAttribute(hmma_gemm_kernel<1>,
                             cudaFuncAttributeMaxDynamicSharedMemorySize, 81920);
        attrs_set = true;
    }

    rope_table_kernel<<<(CT * 32 + 255) / 256, 256>>>();

    {
        dim3 g1(C3 / 128, CM / 128);
        hmma_gemm_kernel<0><<<g1, 512, 81920>>>(x, W_attn, nullptr);
    }
    {
        dim3 g2(CT / 128, CB * CH);
        attn_hmma_kernel<<<g2, 256, 73728>>>();
    }
    {
        dim3 g3(CC / 128, CM / 128);
        hmma_gemm_kernel<1><<<g3, 512, 81920>>>(nullptr, W_proj, out);
    }
}